// round 5
// baseline (speedup 1.0000x reference)
#include <cuda_runtime.h>
#include <math.h>

#define BB 2
#define HH 384
#define WW 512
#define NN (HH*WW)          // 196608 pixels
#define TT (1<<20)
#define TMASK (TT-1)
#define H1 192
#define W1 256
#define H2 96
#define W2 128
#define NBLK 768            // (NN+255)/256
#define NGB 32              // groupnorm partial blocks

// ------------------------- static device scratch -------------------------
__device__ float d_inp[BB*6*NN];
__device__ float d_x1[BB*16*H1*W1];
__device__ float d_x2[BB*16*H2*W2];
__device__ float d_dx1[BB*16*H2*W2];
__device__ float d_catb[BB*32*H1*W1];
__device__ float d_dx2[BB*16*H1*W1];
__device__ float d_dx2up[BB*16*NN];
__device__ float d_conf[BB*NN];

__device__ float  d_mpart[(2*BB+1)*64];
__device__ float  d_simg[BB];
__device__ float  d_sfeat[BB];
__device__ float  d_confmax[1];

__device__ double d_gnp[2*BB*NGB*2];
__device__ float  d_gnmean[2*BB];
__device__ float  d_gnrstd[2*BB];

__device__ int    d_pixh[BB*NN];
__device__ int    d_pixc[BB*NN*5];
__device__ unsigned char d_occ[BB*TT];
__device__ int    d_winner[BB*TT];
__device__ int    d_ctab[BB*TT*5];
__device__ int    d_cell2act[BB*TT];
__device__ int    d_actcell[BB*NN];
__device__ int    d_Mcnt[BB];
__device__ int    d_nbr[BB*NN*10];

__device__ float  d_cnt[BB*NN];     // splat counts (original m)
__device__ float  d_ws[BB*NN];      // splat conf
__device__ float  d_mm[BB*NN];      // m2 = n*blur(n)
__device__ float  d_minv[BB*NN];
__device__ float  d_nA[BB*NN];
__device__ float  d_nB[BB*NN];
__device__ float  d_bvv[BB*NN*3];
__device__ float  d_xv[BB*NN*3];
__device__ float  d_rv[BB*NN*3];
__device__ float  d_zv[BB*NN*3];
__device__ float  d_pvv[BB*NN*3];
__device__ float  d_Apv[BB*NN*3];

__device__ double d_pApAcc[BB*3];
__device__ double d_rzAcc0[BB*3];
__device__ double d_rzAcc1[BB*3];

// ------------------------- helpers -------------------------
__device__ __forceinline__ int hash5i(int c0,int c1,int c2,int c3,int c4){
    unsigned s = (unsigned)c0*73856093u + (unsigned)c1*19349663u + (unsigned)c2*83492791u
               + (unsigned)c3*49979687u + (unsigned)c4*24036583u;
    return (int)(s & (unsigned)TMASK);
}

__device__ __forceinline__ void blockReduce3Atomic(double* loc, double* acc, int b){
    __shared__ double sh[256];
#pragma unroll
    for(int ch=0; ch<3; ch++){
        sh[threadIdx.x]=loc[ch]; __syncthreads();
        for(int s=128;s>0;s>>=1){
            if(threadIdx.x<s) sh[threadIdx.x]+=sh[threadIdx.x+s];
            __syncthreads();
        }
        if(threadIdx.x==0) atomicAdd(&acc[b*3+ch], sh[0]);
        __syncthreads();
    }
}

// ------------------------- max reductions -------------------------
__global__ void k_maxpart(const float* __restrict__ x, int perBatch, float* dst){
    int b = blockIdx.y;
    const float* p = x + (size_t)b*perBatch;
    float m = -1e30f;
    for(int i=blockIdx.x*256+threadIdx.x;i<perBatch;i+=gridDim.x*256)
        m = fmaxf(m, p[i]);
    __shared__ float sh[256];
    sh[threadIdx.x]=m; __syncthreads();
    for(int s=128;s>0;s>>=1){
        if(threadIdx.x<s) sh[threadIdx.x]=fmaxf(sh[threadIdx.x],sh[threadIdx.x+s]);
        __syncthreads();
    }
    if(threadIdx.x==0) dst[b*gridDim.x+blockIdx.x]=sh[0];
}

__global__ void k_maxfin(const float* part, float* sdst, int clipMode){
    int b = blockIdx.x;
    __shared__ float sh[64];
    sh[threadIdx.x]=part[b*64+threadIdx.x]; __syncthreads();
    for(int s=32;s>0;s>>=1){
        if(threadIdx.x<s) sh[threadIdx.x]=fmaxf(sh[threadIdx.x],sh[threadIdx.x+s]);
        __syncthreads();
    }
    if(threadIdx.x==0){
        float v=sh[0];
        if(clipMode==0) v = fminf(fmaxf(v,1e-5f),1.0f);   // _norm_max clip
        else            v = fmaxf(v,1e-5f);                // conf max
        sdst[b]=v;
    }
}

// ------------------------- CNN -------------------------
__global__ void k_makeinp(const float* __restrict__ image, const float* __restrict__ pred){
    int i = blockIdx.x*256+threadIdx.x;
    if(i>=BB*3*NN) return;
    int b = i/(3*NN);
    int r = i - b*3*NN;
    d_inp[b*6*NN + r]        = image[i] / d_simg[b];
    d_inp[b*6*NN + 3*NN + r] = pred[i];
}

template<int IC,int OC,int K,int S,bool EDGE>
__global__ void k_conv(const float* __restrict__ in,int IH,int IW,
                       float* __restrict__ out,int OH,int OW,
                       const float* __restrict__ wt,const float* __restrict__ bs){
    __shared__ float sw[OC*IC*K*K];
    int tid = threadIdx.y*32+threadIdx.x;
    // store transposed: [ic*K*K + ky*K + kx][oc]
    for(int i=tid;i<OC*IC*K*K;i+=256){
        int oc = i/(IC*K*K);
        int rest = i - oc*IC*K*K;
        sw[rest*OC+oc]=wt[i];
    }
    __syncthreads();
    int ox = blockIdx.x*32+threadIdx.x;
    int oy = blockIdx.y*8+threadIdx.y;
    int b  = blockIdx.z;
    if(ox>=OW||oy>=OH) return;
    float acc[OC];
#pragma unroll
    for(int oc=0;oc<OC;oc++) acc[oc]=bs[oc];
    for(int ic=0;ic<IC;ic++){
        const float* ip = in + ((size_t)(b*IC+ic))*IH*IW;
#pragma unroll
        for(int ky=0;ky<K;ky++){
            int iy = oy*S - 1 + ky;
            if(EDGE) iy = min(max(iy,0),IH-1);
            else if(iy<0||iy>=IH) continue;
#pragma unroll
            for(int kx=0;kx<K;kx++){
                int ix = ox*S - 1 + kx;
                if(EDGE) ix = min(max(ix,0),IW-1);
                else if(ix<0||ix>=IW) continue;
                float v = ip[iy*IW+ix];
                const float* w = &sw[((ic*K+ky)*K+kx)*OC];
#pragma unroll
                for(int oc=0;oc<OC;oc++)
                    acc[oc]=fmaf(v,w[oc],acc[oc]);
            }
        }
    }
#pragma unroll
    for(int oc=0;oc<OC;oc++)
        out[((size_t)(b*OC+oc)*OH+oy)*OW+ox]=acc[oc];
}

__global__ void k_gnpart(const float* __restrict__ raw,int HW){
    int grp = blockIdx.y;                // b*2+g
    int b = grp>>1, g = grp&1;
    const float* base = raw + (size_t)(b*16+g*8)*HW;
    int cnt = 8*HW;
    double s=0,q=0;
    for(int i=blockIdx.x*256+threadIdx.x;i<cnt;i+=gridDim.x*256){
        double v = base[i]; s+=v; q+=v*v;
    }
    __shared__ double sh[256],sh2[256];
    sh[threadIdx.x]=s; sh2[threadIdx.x]=q; __syncthreads();
    for(int st=128;st>0;st>>=1){
        if(threadIdx.x<st){sh[threadIdx.x]+=sh[threadIdx.x+st];sh2[threadIdx.x]+=sh2[threadIdx.x+st];}
        __syncthreads();
    }
    if(threadIdx.x==0){
        d_gnp[(grp*NGB+blockIdx.x)*2]=sh[0];
        d_gnp[(grp*NGB+blockIdx.x)*2+1]=sh2[0];
    }
}

__global__ void k_gnfin(int HW){
    int grp = blockIdx.x;
    double s=0,q=0;
    for(int i=threadIdx.x;i<NGB;i+=32){
        s+=d_gnp[(grp*NGB+i)*2];
        q+=d_gnp[(grp*NGB+i)*2+1];
    }
    for(int off=16;off;off>>=1){
        s+=__shfl_down_sync(0xffffffffu,s,off);
        q+=__shfl_down_sync(0xffffffffu,q,off);
    }
    if(threadIdx.x==0){
        double n = 8.0*HW;
        double mean = s/n;
        double var  = q/n - mean*mean;
        d_gnmean[grp]=(float)mean;
        d_gnrstd[grp]=(float)(1.0/sqrt(var+1e-5));
    }
}

__global__ void k_gnapply(float* __restrict__ x,int HW,
                          const float* __restrict__ gam,const float* __restrict__ bet){
    int i = blockIdx.x*256+threadIdx.x;
    if(i>=BB*16*HW) return;
    int c = (i/HW)&15;
    int b = i/(16*HW);
    int grp = b*2 + (c>>3);
    float v = (x[i]-d_gnmean[grp])*d_gnrstd[grp]*gam[c]+bet[c];
    x[i]=fmaxf(v,0.0f);
}

// 2x bilinear upsample, jax.image.resize 'linear' semantics (half-pixel, edge clamp)
__global__ void k_resize2x(const float* __restrict__ in,int IH,int IW,
                           float* __restrict__ out,int outCtot,int chOff){
    int OH=IH*2, OW=IW*2;
    int total=BB*16*OH*OW;
    int i=blockIdx.x*256+threadIdx.x;
    if(i>=total) return;
    int ox=i%OW; int rest=i/OW;
    int oy=rest%OH; rest/=OH;
    int c=rest%16; int b=rest/16;
    float cy=oy*0.5f-0.25f, cx=ox*0.5f-0.25f;
    int y0=(int)floorf(cy); float fy=cy-(float)y0;
    int x0=(int)floorf(cx); float fx=cx-(float)x0;
    int y1=min(y0+1,IH-1), x1=min(x0+1,IW-1);
    y0=max(y0,0); x0=max(x0,0);
    const float* ip = in + ((size_t)(b*16+c))*IH*IW;
    float v00=ip[y0*IW+x0], v01=ip[y0*IW+x1];
    float v10=ip[y1*IW+x0], v11=ip[y1*IW+x1];
    float top=v00+fx*(v01-v00);
    float bot=v10+fx*(v11-v10);
    out[((size_t)(b*outCtot+chOff+c)*OH+oy)*OW+ox]=top+fy*(bot-top);
}

__global__ void k_copy16(){
    int i=blockIdx.x*256+threadIdx.x;
    int HW=H1*W1;
    if(i>=BB*16*HW) return;
    int p=i%HW; int c=(i/HW)&15; int b=i/(16*HW);
    d_catb[((size_t)(b*32+16+c))*HW+p]=d_x1[((size_t)(b*16+c))*HW+p];
}

__global__ void k_tanhconf(){
    int i=blockIdx.x*256+threadIdx.x;
    if(i>=BB*NN) return;
    d_conf[i]=0.5f*(tanhf(d_conf[i])+1.0f);
}

// ------------------------- bilateral grid -------------------------
__global__ void k_hash(const float* __restrict__ feature){
    int pix=blockIdx.x*256+threadIdx.x;
    int b=blockIdx.y;
    if(pix>=NN) return;
    float s = d_sfeat[b];
    float r  = (feature[((size_t)(b*3+0))*NN+pix]/s)*255.0f;
    float g  = (feature[((size_t)(b*3+1))*NN+pix]/s)*255.0f;
    float bl = (feature[((size_t)(b*3+2))*NN+pix]/s)*255.0f;
    int i = pix/WW, j = pix%WW;
    float Y = fmaf(bl,0.114f,    fmaf(g,0.587f,    r*0.299f));
    float U = fmaf(bl,0.5f,      fmaf(g,-0.331264f,r*(-0.168736f)))+128.0f;
    float V = fmaf(bl,-0.081312f,fmaf(g,-0.418688f,r*0.5f))+128.0f;
    int c0=(int)floorf((float)j/7.0f);
    int c1=(int)floorf((float)i/7.0f);
    int c2=(int)floorf(Y*0.125f);
    int c3=(int)floorf(U*0.5f);
    int c4=(int)floorf(V*0.5f);
    int h=hash5i(c0,c1,c2,c3,c4);
    d_pixh[b*NN+pix]=h;
    int* pc=&d_pixc[((size_t)(b*NN+pix))*5];
    pc[0]=c0;pc[1]=c1;pc[2]=c2;pc[3]=c3;pc[4]=c4;
    d_occ[(size_t)b*TT+h]=1;
    atomicMax(&d_winner[(size_t)b*TT+h],pix);
}

__global__ void k_ctab(){
    int pix=blockIdx.x*256+threadIdx.x;
    int b=blockIdx.y;
    if(pix>=NN) return;
    int h=d_pixh[b*NN+pix];
    if(d_winner[(size_t)b*TT+h]==pix){
        const int* pc=&d_pixc[((size_t)(b*NN+pix))*5];
        int* t=&d_ctab[((size_t)b*TT+h)*5];
        t[0]=pc[0];t[1]=pc[1];t[2]=pc[2];t[3]=pc[3];t[4]=pc[4];
    }
}

__global__ void k_compact(){
    int idx=blockIdx.x*256+threadIdx.x;
    if(idx>=BB*TT) return;
    int b=idx>>20;
    int c=idx&TMASK;
    if(d_occ[idx]){
        int a=atomicAdd(&d_Mcnt[b],1);
        d_actcell[b*NN+a]=c;
        d_cell2act[idx]=a;
    }
}

__global__ void k_nbr(){
    int a=blockIdx.x*256+threadIdx.x;
    int b=blockIdx.y;
    if(a>=d_Mcnt[b]) return;
    int c=d_actcell[b*NN+a];
    const int* me=&d_ctab[((size_t)b*TT+c)*5];
    int cc[5]={me[0],me[1],me[2],me[3],me[4]};
    int* nb=&d_nbr[((size_t)(b*NN+a))*10];
    int k=0;
#pragma unroll
    for(int d=0;d<5;d++){
#pragma unroll
        for(int o=0;o<2;o++){
            int off = o? 1 : -1;
            int nc[5]={cc[0],cc[1],cc[2],cc[3],cc[4]};
            nc[d]+=off;
            int nh=hash5i(nc[0],nc[1],nc[2],nc[3],nc[4]);
            int res=-1;
            if(d_occ[(size_t)b*TT+nh]){
                const int* t=&d_ctab[((size_t)b*TT+nh)*5];
                if(t[0]==nc[0]&&t[1]==nc[1]&&t[2]==nc[2]&&t[3]==nc[3]&&t[4]==nc[4])
                    res=d_cell2act[(size_t)b*TT+nh];
            }
            nb[k++]=res;
        }
    }
    d_nA[b*NN+a]=1.0f;
}

__global__ void k_splat(const float* __restrict__ pred){
    int pix=blockIdx.x*256+threadIdx.x;
    int b=blockIdx.y;
    if(pix>=NN) return;
    int h=d_pixh[b*NN+pix];
    int a=d_cell2act[(size_t)b*TT+h];
    int base=b*NN+a;
    atomicAdd(&d_cnt[base],1.0f);
    float w = d_conf[b*NN+pix]/d_confmax[0];
    atomicAdd(&d_ws[base],w);
#pragma unroll
    for(int ch=0;ch<3;ch++)
        atomicAdd(&d_bvv[base*3+ch], w*pred[((size_t)(b*3+ch))*NN+pix]);
}

__global__ void k_bisto(const float* __restrict__ src,float* __restrict__ dst){
    int a=blockIdx.x*256+threadIdx.x;
    int b=blockIdx.y;
    if(a>=d_Mcnt[b]) return;
    int base=b*NN+a;
    const int* nb=&d_nbr[((size_t)base)*10];
    float v=src[base];
    float s=10.0f*v;
#pragma unroll
    for(int k=0;k<10;k++){
        int id=nb[k];
        if(id>=0) s+=src[b*NN+id];
    }
    dst[base]=sqrtf(v*d_cnt[base]/(s+1e-12f));
}

__global__ void k_prep1(){
    int a=blockIdx.x*256+threadIdx.x;
    int b=blockIdx.y;
    if(a>=d_Mcnt[b]) return;
    int base=b*NN+a;
    const int* nb=&d_nbr[((size_t)base)*10];
    float n=d_nA[base];
    float s=10.0f*n;
#pragma unroll
    for(int k=0;k<10;k++){
        int id=nb[k];
        if(id>=0) s+=d_nA[b*NN+id];
    }
    float m2=n*s;
    d_mm[base]=m2;
    float ws=d_ws[base];
    float Ad=fmaxf(200.0f*(m2-10.0f*n*n)+ws,1e-5f);
    d_minv[base]=1.0f/Ad;
#pragma unroll
    for(int ch=0;ch<3;ch++)
        d_xv[base*3+ch]=d_bvv[base*3+ch]/(ws+1e-12f);
}

// MODE 0: Ap = A(p), accumulate p.Ap  |  MODE 1: init r,z,p from x, accumulate r.z
template<int MODE>
__global__ void k_Ap(const float* __restrict__ v, double* acc, double* clearBuf){
    int a=blockIdx.x*256+threadIdx.x;
    int b=blockIdx.y;
    if(clearBuf!=nullptr && blockIdx.x==0 && b==0 && threadIdx.x<BB*3)
        clearBuf[threadIdx.x]=0.0;
    double loc[3]={0.0,0.0,0.0};
    int M=d_Mcnt[b];
    if(a<M){
        int base=b*NN+a;
        float na=d_nA[base];
        const int* nb=&d_nbr[((size_t)base)*10];
        float v0=v[base*3+0], v1=v[base*3+1], v2=v[base*3+2];
        float t0=0.f,t1=0.f,t2=0.f;
#pragma unroll
        for(int k=0;k<10;k++){
            int id=nb[k];
            if(id>=0){
                float nn=d_nA[b*NN+id];
                const float* pv=&v[((size_t)(b*NN+id))*3];
                t0=fmaf(nn,pv[0],t0);
                t1=fmaf(nn,pv[1],t1);
                t2=fmaf(nn,pv[2],t2);
            }
        }
        float mm=d_mm[base], ws=d_ws[base];
        float Ap0=200.0f*(mm*v0-na*(10.0f*na*v0+t0))+ws*v0;
        float Ap1=200.0f*(mm*v1-na*(10.0f*na*v1+t1))+ws*v1;
        float Ap2=200.0f*(mm*v2-na*(10.0f*na*v2+t2))+ws*v2;
        if(MODE==0){
            d_Apv[base*3+0]=Ap0; d_Apv[base*3+1]=Ap1; d_Apv[base*3+2]=Ap2;
            loc[0]=(double)v0*Ap0; loc[1]=(double)v1*Ap1; loc[2]=(double)v2*Ap2;
        }else{
            float mi=d_minv[base];
            float r0=d_bvv[base*3+0]-Ap0, r1=d_bvv[base*3+1]-Ap1, r2=d_bvv[base*3+2]-Ap2;
            d_rv[base*3+0]=r0; d_rv[base*3+1]=r1; d_rv[base*3+2]=r2;
            float z0=mi*r0, z1=mi*r1, z2=mi*r2;
            d_zv[base*3+0]=z0; d_zv[base*3+1]=z1; d_zv[base*3+2]=z2;
            d_pvv[base*3+0]=z0; d_pvv[base*3+1]=z1; d_pvv[base*3+2]=z2;
            loc[0]=(double)r0*z0; loc[1]=(double)r1*z1; loc[2]=(double)r2*z2;
        }
    }
    blockReduce3Atomic(loc,acc,b);
}

__global__ void k_upd1(const double* __restrict__ rzPrev, const double* __restrict__ pAp,
                       double* rzNew){
    int a=blockIdx.x*256+threadIdx.x;
    int b=blockIdx.y;
    double loc[3]={0.0,0.0,0.0};
    int M=d_Mcnt[b];
    if(a<M){
        int base=b*NN+a;
        float mi=d_minv[base];
#pragma unroll
        for(int ch=0;ch<3;ch++){
            float alpha=(float)rzPrev[b*3+ch]/((float)pAp[b*3+ch]+1e-12f);
            float p=d_pvv[base*3+ch], Ap=d_Apv[base*3+ch];
            d_xv[base*3+ch]+=alpha*p;
            float r=d_rv[base*3+ch]-alpha*Ap;
            d_rv[base*3+ch]=r;
            float z=mi*r;
            d_zv[base*3+ch]=z;
            loc[ch]=(double)r*z;
        }
    }
    blockReduce3Atomic(loc,rzNew,b);
}

__global__ void k_upd2(const double* __restrict__ rzNew, const double* __restrict__ rzOld,
                       double* pApClear){
    int a=blockIdx.x*256+threadIdx.x;
    int b=blockIdx.y;
    if(blockIdx.x==0 && b==0 && threadIdx.x<BB*3) pApClear[threadIdx.x]=0.0;
    if(a>=d_Mcnt[b]) return;
    int base=b*NN+a;
#pragma unroll
    for(int ch=0;ch<3;ch++){
        float beta=(float)rzNew[b*3+ch]/((float)rzOld[b*3+ch]+1e-12f);
        d_pvv[base*3+ch]=d_zv[base*3+ch]+beta*d_pvv[base*3+ch];
    }
}

__global__ void k_output(float* __restrict__ out){
    int i=blockIdx.x*256+threadIdx.x;
    if(i>=BB*4*NN) return;
    int pix=i%NN; int rest=i/NN;
    int ch=rest%4; int b=rest/4;
    if(ch<3){
        int h=d_pixh[b*NN+pix];
        int a=d_cell2act[(size_t)b*TT+h];
        out[((size_t)(b*3+ch))*NN+pix]=d_xv[((size_t)(b*NN+a))*3+ch];
    }else{
        out[(size_t)BB*3*NN + (size_t)b*NN+pix]=d_conf[b*NN+pix]/d_confmax[0];
    }
}

// ------------------------- host -------------------------
extern "C" void kernel_launch(void* const* d_in, const int* in_sizes, int n_in,
                              void* d_out, int out_size){
    const float* image  =(const float*)d_in[0];
    const float* feature=(const float*)d_in[1];
    const float* pred   =(const float*)d_in[2];
    const float* w1 =(const float*)d_in[3];  const float* b1 =(const float*)d_in[4];
    const float* g1 =(const float*)d_in[5];  const float* be1=(const float*)d_in[6];
    const float* w2 =(const float*)d_in[7];  const float* b2 =(const float*)d_in[8];
    const float* g2 =(const float*)d_in[9];  const float* be2=(const float*)d_in[10];
    const float* wd1=(const float*)d_in[11]; const float* bd1=(const float*)d_in[12];
    const float* gd1=(const float*)d_in[13]; const float* bed1=(const float*)d_in[14];
    const float* wd2=(const float*)d_in[15]; const float* bd2=(const float*)d_in[16];
    const float* gd2=(const float*)d_in[17]; const float* bed2=(const float*)d_in[18];
    const float* wf =(const float*)d_in[19]; const float* bf =(const float*)d_in[20];
    float* out=(float*)d_out;

    // CRITICAL: __device__ symbols must be resolved via cudaGetSymbolAddress
    // before being passed as kernel arguments (the bare symbol in host code is
    // the host shadow; on GB300/ATS the device silently reads host memory).
    void *p_occ,*p_win,*p_mcnt,*p_cnt,*p_ws,*p_bv,*p_pap,*p_rz0,*p_rz1;
    void *p_mpart,*p_simg,*p_sfeat,*p_cmax;
    void *p_inp,*p_x1,*p_x2,*p_dx1,*p_catb,*p_dx2,*p_dx2up,*p_conf;
    void *p_nA,*p_nB,*p_xv,*p_pv;
    cudaGetSymbolAddress(&p_occ,  d_occ);
    cudaGetSymbolAddress(&p_win,  d_winner);
    cudaGetSymbolAddress(&p_mcnt, d_Mcnt);
    cudaGetSymbolAddress(&p_cnt,  d_cnt);
    cudaGetSymbolAddress(&p_ws,   d_ws);
    cudaGetSymbolAddress(&p_bv,   d_bvv);
    cudaGetSymbolAddress(&p_pap,  d_pApAcc);
    cudaGetSymbolAddress(&p_rz0,  d_rzAcc0);
    cudaGetSymbolAddress(&p_rz1,  d_rzAcc1);
    cudaGetSymbolAddress(&p_mpart,d_mpart);
    cudaGetSymbolAddress(&p_simg, d_simg);
    cudaGetSymbolAddress(&p_sfeat,d_sfeat);
    cudaGetSymbolAddress(&p_cmax, d_confmax);
    cudaGetSymbolAddress(&p_inp,  d_inp);
    cudaGetSymbolAddress(&p_x1,   d_x1);
    cudaGetSymbolAddress(&p_x2,   d_x2);
    cudaGetSymbolAddress(&p_dx1,  d_dx1);
    cudaGetSymbolAddress(&p_catb, d_catb);
    cudaGetSymbolAddress(&p_dx2,  d_dx2);
    cudaGetSymbolAddress(&p_dx2up,d_dx2up);
    cudaGetSymbolAddress(&p_conf, d_conf);
    cudaGetSymbolAddress(&p_nA,   d_nA);
    cudaGetSymbolAddress(&p_nB,   d_nB);
    cudaGetSymbolAddress(&p_xv,   d_xv);
    cudaGetSymbolAddress(&p_pv,   d_pvv);

    double* pAp=(double*)p_pap;
    double* RZ[2]={(double*)p_rz0,(double*)p_rz1};
    float* mpart=(float*)p_mpart;

    cudaMemsetAsync(p_occ, 0,   (size_t)BB*TT);
    cudaMemsetAsync(p_win, 0xFF,(size_t)BB*TT*4);
    cudaMemsetAsync(p_mcnt,0,   BB*sizeof(int));
    cudaMemsetAsync(p_cnt, 0,   (size_t)BB*NN*4);
    cudaMemsetAsync(p_ws,  0,   (size_t)BB*NN*4);
    cudaMemsetAsync(p_bv,  0,   (size_t)BB*NN*12);
    cudaMemsetAsync(p_pap, 0,   BB*3*sizeof(double));
    cudaMemsetAsync(p_rz0, 0,   BB*3*sizeof(double));
    cudaMemsetAsync(p_rz1, 0,   BB*3*sizeof(double));

    // ---- norm_max scales ----
    k_maxpart<<<dim3(64,BB),256>>>(image,  3*NN, mpart);
    k_maxpart<<<dim3(64,BB),256>>>(feature,3*NN, mpart+BB*64);
    k_maxfin<<<BB,64>>>(mpart,        (float*)p_simg, 0);
    k_maxfin<<<BB,64>>>(mpart+BB*64,  (float*)p_sfeat,0);

    // ---- CNN ----
    k_makeinp<<<(BB*3*NN+255)/256,256>>>(image,pred);

    dim3 cth(32,8);
    k_conv<6,16,4,2,true><<<dim3(8,24,BB),cth>>>(
        (const float*)p_inp,HH,WW,(float*)p_x1,H1,W1,w1,b1);
    { int HW=H1*W1;
      k_gnpart<<<dim3(NGB,2*BB),256>>>((const float*)p_x1,HW);
      k_gnfin<<<2*BB,32>>>(HW);
      k_gnapply<<<(BB*16*HW+255)/256,256>>>((float*)p_x1,HW,g1,be1); }

    k_conv<16,16,4,2,true><<<dim3(4,12,BB),cth>>>(
        (const float*)p_x1,H1,W1,(float*)p_x2,H2,W2,w2,b2);
    { int HW=H2*W2;
      k_gnpart<<<dim3(NGB,2*BB),256>>>((const float*)p_x2,HW);
      k_gnfin<<<2*BB,32>>>(HW);
      k_gnapply<<<(BB*16*HW+255)/256,256>>>((float*)p_x2,HW,g2,be2); }

    k_conv<16,16,3,1,false><<<dim3(4,12,BB),cth>>>(
        (const float*)p_x2,H2,W2,(float*)p_dx1,H2,W2,wd1,bd1);
    { int HW=H2*W2;
      k_gnpart<<<dim3(NGB,2*BB),256>>>((const float*)p_dx1,HW);
      k_gnfin<<<2*BB,32>>>(HW);
      k_gnapply<<<(BB*16*HW+255)/256,256>>>((float*)p_dx1,HW,gd1,bed1); }

    k_resize2x<<<(BB*16*H1*W1+255)/256,256>>>((const float*)p_dx1,H2,W2,(float*)p_catb,32,0);
    k_copy16<<<(BB*16*H1*W1+255)/256,256>>>();

    k_conv<32,16,3,1,false><<<dim3(8,24,BB),cth>>>(
        (const float*)p_catb,H1,W1,(float*)p_dx2,H1,W1,wd2,bd2);
    { int HW=H1*W1;
      k_gnpart<<<dim3(NGB,2*BB),256>>>((const float*)p_dx2,HW);
      k_gnfin<<<2*BB,32>>>(HW);
      k_gnapply<<<(BB*16*HW+255)/256,256>>>((float*)p_dx2,HW,gd2,bed2); }

    k_resize2x<<<(BB*16*NN+255)/256,256>>>((const float*)p_dx2,H1,W1,(float*)p_dx2up,16,0);

    k_conv<16,1,3,1,true><<<dim3(16,48,BB),cth>>>(
        (const float*)p_dx2up,HH,WW,(float*)p_conf,HH,WW,wf,bf);
    k_tanhconf<<<(BB*NN+255)/256,256>>>();
    k_maxpart<<<dim3(64,1),256>>>((const float*)p_conf, BB*NN, mpart+2*BB*64);
    k_maxfin<<<1,64>>>(mpart+2*BB*64,(float*)p_cmax,1);

    // ---- bilateral grid build ----
    k_hash<<<dim3(NBLK,BB),256>>>(feature);
    k_ctab<<<dim3(NBLK,BB),256>>>();
    k_compact<<<(BB*TT+255)/256,256>>>();
    k_nbr<<<dim3(NBLK,BB),256>>>();
    k_splat<<<dim3(NBLK,BB),256>>>(pred);

    // ---- bistochastization (10 iters, ping-pong nA/nB) ----
    float* nbuf[2]={(float*)p_nA,(float*)p_nB};
    for(int it=0;it<10;it++)
        k_bisto<<<dim3(NBLK,BB),256>>>(nbuf[it&1],nbuf[(it+1)&1]);
    // 10 iterations -> result ends back in d_nA

    k_prep1<<<dim3(NBLK,BB),256>>>();

    // r,z,p init + S(0) -> RZ[0]
    k_Ap<1><<<dim3(NBLK,BB),256>>>((const float*)p_xv, RZ[0], nullptr);

    for(int it=0;it<12;it++){
        // Ap(it): Ap=A(p), accumulate p.Ap; clear RZ[(it+1)%2] (upd1 target)
        k_Ap<0><<<dim3(NBLK,BB),256>>>((const float*)p_pv, pAp, RZ[(it+1)&1]);
        // upd1: alpha=S(it)/pAp; x,r,z update; write S(it+1)
        k_upd1<<<dim3(NBLK,BB),256>>>(RZ[it&1], pAp, RZ[(it+1)&1]);
        // upd2: beta=S(it+1)/S(it); p=z+beta*p; clear pAp for next iter
        k_upd2<<<dim3(NBLK,BB),256>>>(RZ[(it+1)&1], RZ[it&1], pAp);
    }

    k_output<<<(BB*4*NN+255)/256,256>>>(out);
}

// round 6
// speedup vs baseline: 1.2611x; 1.2611x over previous
#include <cuda_runtime.h>
#include <math.h>

#define BB 2
#define HH 384
#define WW 512
#define NN (HH*WW)          // 196608 pixels
#define TT (1<<20)
#define TMASK (TT-1)
#define H1 192
#define W1 256
#define H2 96
#define W2 128
#define NGB 32
#define MAXG 1024

// ------------------------- CNN scratch -------------------------
__device__ float d_inp[BB*6*NN];
__device__ float d_x1[BB*16*H1*W1];
__device__ float d_x2[BB*16*H2*W2];
__device__ float d_dx1[BB*16*H2*W2];
__device__ float d_catb[BB*32*H1*W1];
__device__ float d_dx2[BB*16*H1*W1];
__device__ float d_dx2up[BB*16*NN];
__device__ float d_conf[BB*NN];

__device__ float  d_mpart[2*BB*64];
__device__ float  d_simg[BB];
__device__ float  d_sfeat[BB];

__device__ double d_gnp[2*BB*NGB*2];
__device__ float  d_gnmean[2*BB];
__device__ float  d_gnrstd[2*BB];

// ------------------------- solver scratch -------------------------
__device__ int    d_pixh[BB*NN];
__device__ int    d_pixa[BB*NN];
__device__ int    d_winner[BB*TT];
__device__ int    d_ctab[BB*TT*5];
__device__ int    d_cell2act[BB*TT];
__device__ int    d_actcell[BB*NN];
__device__ int    d_Mcnt[BB];
__device__ int    d_nbr[BB*NN*10];
__device__ float  d_ew[BB*NN*10];

__device__ float  d_cnt[BB*NN];
__device__ float  d_ws[BB*NN];
__device__ float  d_nA[BB*NN];
__device__ float  d_nB[BB*NN];
__device__ float  d_diag[BB*NN];
__device__ float  d_minv[BB*NN];
__device__ float4 d_b4[BB*NN];
__device__ float4 d_x4[BB*NN];
__device__ float4 d_r4[BB*NN];
__device__ float4 d_z4[BB*NN];
__device__ float4 d_p4[BB*NN];
__device__ float4 d_Ap4[BB*NN];

__device__ float  d_cpart[MAXG];
__device__ double d_pappart[12*6*MAXG];
__device__ double d_rzpart[13*6*MAXG];

// barrier state (self-cleaning across graph replays)
__device__ unsigned d_sub[8];
__device__ unsigned d_root;
__device__ volatile unsigned d_phase;

// ------------------------- helpers -------------------------
__device__ __forceinline__ int hash5i(int c0,int c1,int c2,int c3,int c4){
    unsigned s = (unsigned)c0*73856093u + (unsigned)c1*19349663u + (unsigned)c2*83492791u
               + (unsigned)c3*49979687u + (unsigned)c4*24036583u;
    return (int)(s & (unsigned)TMASK);
}

__device__ __forceinline__ void pix_coords(const float* __restrict__ feature,int b,int pix,int* c){
    float s = d_sfeat[b];
    float r  = (feature[(size_t)(b*3+0)*NN+pix]/s)*255.0f;
    float g  = (feature[(size_t)(b*3+1)*NN+pix]/s)*255.0f;
    float bl = (feature[(size_t)(b*3+2)*NN+pix]/s)*255.0f;
    int i = pix/WW, j = pix - i*WW;
    float Y = fmaf(bl,0.114f,    fmaf(g,0.587f,    r*0.299f));
    float U = fmaf(bl,0.5f,      fmaf(g,-0.331264f,r*(-0.168736f)))+128.0f;
    float V = fmaf(bl,-0.081312f,fmaf(g,-0.418688f,r*0.5f))+128.0f;
    c[0]=(int)floorf((float)j/7.0f);
    c[1]=(int)floorf((float)i/7.0f);
    c[2]=(int)floorf(Y*0.125f);
    c[3]=(int)floorf(U*0.5f);
    c[4]=(int)floorf(V*0.5f);
}

// grid-wide barrier: two-level arrival, phase-flag release.
__device__ __forceinline__ void gridbar(){
    __syncthreads();
    if(threadIdx.x==0){
        __threadfence();
        unsigned gen = d_phase;
        unsigned G = gridDim.x;
        unsigned g = blockIdx.x & 7u;
        unsigned gsz = (G - g + 7u) >> 3;
        unsigned t = atomicInc(&d_sub[g], gsz-1u);
        if(t == gsz-1u){
            unsigned r = atomicInc(&d_root, 7u);
            if(r == 7u){
                __threadfence();
                d_phase = gen+1u;
            }
        }
        while(d_phase == gen){}
    }
    __syncthreads();
    __threadfence();   // acquire: flush L1 so post-barrier reads are fresh
}

// block-reduce 6 doubles -> per-block partial slot (layout [6][G], channel-major)
__device__ __forceinline__ void partout6(double* acc, double* dst, int G){
    __shared__ double s_red[16][6];
    int wp=threadIdx.x>>5, ln=threadIdx.x&31;
#pragma unroll
    for(int c=0;c<6;c++){
        double v=acc[c];
        for(int off=16;off;off>>=1) v+=__shfl_down_sync(0xffffffffu,v,off);
        if(ln==0) s_red[wp][c]=v;
    }
    __syncthreads();
    if(threadIdx.x<6){
        double s=0; int nw=blockDim.x>>5;
        for(int w=0;w<nw;w++) s+=s_red[w][threadIdx.x];
        dst[threadIdx.x*G + blockIdx.x]=s;
    }
    __syncthreads();
}

// reduce partials [6][G] into smem float[6] (warps 0..5)
__device__ __forceinline__ void reduce6f(const double* src, int G, float* out6){
    int wp=threadIdx.x>>5, ln=threadIdx.x&31;
    if(wp<6){
        double s=0;
        for(int i=ln;i<G;i+=32) s+=src[wp*G+i];
        for(int off=16;off;off>>=1) s+=__shfl_down_sync(0xffffffffu,s,off);
        if(ln==0) out6[wp]=(float)s;
    }
    __syncthreads();
}

// ------------------------- CNN kernels (unchanged, known-good) -------------------------
__global__ void k_maxpart(const float* __restrict__ x, int perBatch, float* dst){
    int b = blockIdx.y;
    const float* p = x + (size_t)b*perBatch;
    float m = -1e30f;
    for(int i=blockIdx.x*256+threadIdx.x;i<perBatch;i+=gridDim.x*256)
        m = fmaxf(m, p[i]);
    __shared__ float sh[256];
    sh[threadIdx.x]=m; __syncthreads();
    for(int s=128;s>0;s>>=1){
        if(threadIdx.x<s) sh[threadIdx.x]=fmaxf(sh[threadIdx.x],sh[threadIdx.x+s]);
        __syncthreads();
    }
    if(threadIdx.x==0) dst[b*gridDim.x+blockIdx.x]=sh[0];
}

__global__ void k_maxfin(const float* part, float* sdst){
    int b = blockIdx.x;
    __shared__ float sh[64];
    sh[threadIdx.x]=part[b*64+threadIdx.x]; __syncthreads();
    for(int s=32;s>0;s>>=1){
        if(threadIdx.x<s) sh[threadIdx.x]=fmaxf(sh[threadIdx.x],sh[threadIdx.x+s]);
        __syncthreads();
    }
    if(threadIdx.x==0) sdst[b]=fminf(fmaxf(sh[0],1e-5f),1.0f);
}

__global__ void k_makeinp(const float* __restrict__ image, const float* __restrict__ pred){
    int i = blockIdx.x*256+threadIdx.x;
    if(i>=BB*3*NN) return;
    int b = i/(3*NN);
    int r = i - b*3*NN;
    d_inp[b*6*NN + r]        = image[i] / d_simg[b];
    d_inp[b*6*NN + 3*NN + r] = pred[i];
}

template<int IC,int OC,int K,int S,bool EDGE>
__global__ void k_conv(const float* __restrict__ in,int IH,int IW,
                       float* __restrict__ out,int OH,int OW,
                       const float* __restrict__ wt,const float* __restrict__ bs){
    __shared__ float sw[OC*IC*K*K];
    int tid = threadIdx.y*32+threadIdx.x;
    for(int i=tid;i<OC*IC*K*K;i+=256){
        int oc = i/(IC*K*K);
        int rest = i - oc*IC*K*K;
        sw[rest*OC+oc]=wt[i];
    }
    __syncthreads();
    int ox = blockIdx.x*32+threadIdx.x;
    int oy = blockIdx.y*8+threadIdx.y;
    int b  = blockIdx.z;
    if(ox>=OW||oy>=OH) return;
    float acc[OC];
#pragma unroll
    for(int oc=0;oc<OC;oc++) acc[oc]=bs[oc];
    for(int ic=0;ic<IC;ic++){
        const float* ip = in + ((size_t)(b*IC+ic))*IH*IW;
#pragma unroll
        for(int ky=0;ky<K;ky++){
            int iy = oy*S - 1 + ky;
            if(EDGE) iy = min(max(iy,0),IH-1);
            else if(iy<0||iy>=IH) continue;
#pragma unroll
            for(int kx=0;kx<K;kx++){
                int ix = ox*S - 1 + kx;
                if(EDGE) ix = min(max(ix,0),IW-1);
                else if(ix<0||ix>=IW) continue;
                float v = ip[iy*IW+ix];
                const float* w = &sw[((ic*K+ky)*K+kx)*OC];
#pragma unroll
                for(int oc=0;oc<OC;oc++)
                    acc[oc]=fmaf(v,w[oc],acc[oc]);
            }
        }
    }
#pragma unroll
    for(int oc=0;oc<OC;oc++)
        out[((size_t)(b*OC+oc)*OH+oy)*OW+ox]=acc[oc];
}

__global__ void k_gnpart(const float* __restrict__ raw,int HW){
    int grp = blockIdx.y;
    int b = grp>>1, g = grp&1;
    const float* base = raw + (size_t)(b*16+g*8)*HW;
    int cnt = 8*HW;
    double s=0,q=0;
    for(int i=blockIdx.x*256+threadIdx.x;i<cnt;i+=gridDim.x*256){
        double v = base[i]; s+=v; q+=v*v;
    }
    __shared__ double sh[256],sh2[256];
    sh[threadIdx.x]=s; sh2[threadIdx.x]=q; __syncthreads();
    for(int st=128;st>0;st>>=1){
        if(threadIdx.x<st){sh[threadIdx.x]+=sh[threadIdx.x+st];sh2[threadIdx.x]+=sh2[threadIdx.x+st];}
        __syncthreads();
    }
    if(threadIdx.x==0){
        d_gnp[(grp*NGB+blockIdx.x)*2]=sh[0];
        d_gnp[(grp*NGB+blockIdx.x)*2+1]=sh2[0];
    }
}

__global__ void k_gnfin(int HW){
    int grp = blockIdx.x;
    double s=0,q=0;
    for(int i=threadIdx.x;i<NGB;i+=32){
        s+=d_gnp[(grp*NGB+i)*2];
        q+=d_gnp[(grp*NGB+i)*2+1];
    }
    for(int off=16;off;off>>=1){
        s+=__shfl_down_sync(0xffffffffu,s,off);
        q+=__shfl_down_sync(0xffffffffu,q,off);
    }
    if(threadIdx.x==0){
        double n = 8.0*HW;
        double mean = s/n;
        double var  = q/n - mean*mean;
        d_gnmean[grp]=(float)mean;
        d_gnrstd[grp]=(float)(1.0/sqrt(var+1e-5));
    }
}

__global__ void k_gnapply(float* __restrict__ x,int HW,
                          const float* __restrict__ gam,const float* __restrict__ bet){
    int i = blockIdx.x*256+threadIdx.x;
    if(i>=BB*16*HW) return;
    int c = (i/HW)&15;
    int b = i/(16*HW);
    int grp = b*2 + (c>>3);
    float v = (x[i]-d_gnmean[grp])*d_gnrstd[grp]*gam[c]+bet[c];
    x[i]=fmaxf(v,0.0f);
}

__global__ void k_resize2x(const float* __restrict__ in,int IH,int IW,
                           float* __restrict__ out,int outCtot,int chOff){
    int OH=IH*2, OW=IW*2;
    int total=BB*16*OH*OW;
    int i=blockIdx.x*256+threadIdx.x;
    if(i>=total) return;
    int ox=i%OW; int rest=i/OW;
    int oy=rest%OH; rest/=OH;
    int c=rest%16; int b=rest/16;
    float cy=oy*0.5f-0.25f, cx=ox*0.5f-0.25f;
    int y0=(int)floorf(cy); float fy=cy-(float)y0;
    int x0=(int)floorf(cx); float fx=cx-(float)x0;
    int y1=min(y0+1,IH-1), x1=min(x0+1,IW-1);
    y0=max(y0,0); x0=max(x0,0);
    const float* ip = in + ((size_t)(b*16+c))*IH*IW;
    float v00=ip[y0*IW+x0], v01=ip[y0*IW+x1];
    float v10=ip[y1*IW+x0], v11=ip[y1*IW+x1];
    float top=v00+fx*(v01-v00);
    float bot=v10+fx*(v11-v10);
    out[((size_t)(b*outCtot+chOff+c)*OH+oy)*OW+ox]=top+fy*(bot-top);
}

__global__ void k_copy16(){
    int i=blockIdx.x*256+threadIdx.x;
    int HW=H1*W1;
    if(i>=BB*16*HW) return;
    int p=i%HW; int c=(i/HW)&15; int b=i/(16*HW);
    d_catb[((size_t)(b*32+16+c))*HW+p]=d_x1[((size_t)(b*16+c))*HW+p];
}

__global__ void k_tanhconf(){
    int i=blockIdx.x*256+threadIdx.x;
    if(i>=BB*NN) return;
    d_conf[i]=0.5f*(tanhf(d_conf[i])+1.0f);
}

// ------------------------- persistent bilateral solver -------------------------
__global__ void __launch_bounds__(512) k_solver(const float* __restrict__ feature,
                                               const float* __restrict__ pred,
                                               float* __restrict__ out){
    const int T   = blockDim.x*gridDim.x;
    const int tid = blockIdx.x*blockDim.x + threadIdx.x;
    const int G   = gridDim.x;
    const int wp  = threadIdx.x>>5, ln = threadIdx.x&31;

    __shared__ float s_w[16];
    __shared__ float s_cmax;
    __shared__ float s_rz[6], s_pap[6], s_rzn[6];
    __shared__ float s_alpha[6], s_beta[6];

    // ---------- Ph0: clears + conf-max partial ----------
    for(int i=tid;i<BB*TT;i+=T) d_winner[i]=-1;
    if(tid<BB) d_Mcnt[tid]=0;
    for(int i=tid;i<BB*NN;i+=T){
        d_cnt[i]=0.f; d_ws[i]=0.f;
        d_b4[i]=make_float4(0.f,0.f,0.f,0.f);
    }
    {
        float cm=-1e30f;
        for(int i=tid;i<BB*NN;i+=T) cm=fmaxf(cm,d_conf[i]);
        for(int off=16;off;off>>=1) cm=fmaxf(cm,__shfl_down_sync(0xffffffffu,cm,off));
        if(ln==0) s_w[wp]=cm;
        __syncthreads();
        if(threadIdx.x==0){
            float m=-1e30f; int nw=blockDim.x>>5;
            for(int w=0;w<nw;w++) m=fmaxf(m,s_w[w]);
            d_cpart[blockIdx.x]=m;
        }
        __syncthreads();
    }
    gridbar();

    // ---------- Ph1: hash ----------
    for(int w=tid;w<BB*NN;w+=T){
        int b = (w>=NN); int pix = w - (b? NN:0);
        int c[5]; pix_coords(feature,b,pix,c);
        int h=hash5i(c[0],c[1],c[2],c[3],c[4]);
        d_pixh[w]=h;
        atomicMax(&d_winner[b*TT+h],pix);
    }
    gridbar();

    // ---------- Ph2: ctab (winner writes its coords) ----------
    for(int w=tid;w<BB*NN;w+=T){
        int b = (w>=NN); int pix = w - (b? NN:0);
        int h = d_pixh[w];
        if(d_winner[b*TT+h]==pix){
            int c[5]; pix_coords(feature,b,pix,c);
            int* t=&d_ctab[(b*TT+h)*5];
            t[0]=c[0];t[1]=c[1];t[2]=c[2];t[3]=c[3];t[4]=c[4];
        }
    }
    gridbar();

    // ---------- Ph3: compact (warp-aggregated atomics) ----------
    for(int i0=0;i0<BB*TT;i0+=T){
        int i=i0+tid;
        bool on = (i<BB*TT) && (d_winner[i]>=0);
        unsigned m=__ballot_sync(0xffffffffu,on);
        if(m){
            int leader=__ffs(m)-1;
            int wbase = i0 + blockIdx.x*blockDim.x + (threadIdx.x & ~31);
            int bb_ = (wbase + leader)>>20;
            int base=0;
            if(ln==leader) base=atomicAdd(&d_Mcnt[bb_],__popc(m));
            base=__shfl_sync(0xffffffffu,base,leader);
            if(on){
                int a=base+__popc(m & ((1u<<ln)-1u));
                d_actcell[bb_*NN+a]=i&TMASK;
                d_cell2act[i]=a;
            }
        }
    }
    gridbar();

    // ---------- Ph4: neighbor build + splat ----------
    for(int w=tid;w<BB*NN;w+=T){
        int b=(w>=NN); int a=w-(b?NN:0);
        if(a<d_Mcnt[b]){
            int cell=d_actcell[b*NN+a];
            const int* me=&d_ctab[(b*TT+cell)*5];
            int cc[5]={me[0],me[1],me[2],me[3],me[4]};
            int* nb=&d_nbr[(size_t)(b*NN+a)*10];
            int k=0;
#pragma unroll
            for(int d=0;d<5;d++){
#pragma unroll
                for(int o=0;o<2;o++){
                    int nc[5]={cc[0],cc[1],cc[2],cc[3],cc[4]};
                    nc[d]+= o?1:-1;
                    int nh=hash5i(nc[0],nc[1],nc[2],nc[3],nc[4]);
                    int res=-1;
                    if(d_winner[b*TT+nh]>=0){
                        const int* t=&d_ctab[(b*TT+nh)*5];
                        if(t[0]==nc[0]&&t[1]==nc[1]&&t[2]==nc[2]&&t[3]==nc[3]&&t[4]==nc[4])
                            res=d_cell2act[b*TT+nh];
                    }
                    nb[k++]=res;
                }
            }
            d_nA[b*NN+a]=1.0f;
        }
    }
    // conf max (reduce partials) then splat
    if(wp==0){
        float m=-1e30f;
        for(int i=ln;i<G;i+=32) m=fmaxf(m,d_cpart[i]);
        for(int off=16;off;off>>=1) m=fmaxf(m,__shfl_down_sync(0xffffffffu,m,off));
        if(ln==0) s_cmax=fmaxf(m,1e-5f);
    }
    __syncthreads();
    {
        float cmax=s_cmax;
        for(int w=tid;w<BB*NN;w+=T){
            int b=(w>=NN); int pix=w-(b?NN:0);
            int h=d_pixh[w];
            int a=d_cell2act[b*TT+h];
            d_pixa[w]=a;
            int base=b*NN+a;
            float wgt=d_conf[w]/cmax;
            atomicAdd(&d_cnt[base],1.0f);
            atomicAdd(&d_ws[base],wgt);
            float p0=pred[(size_t)(b*3+0)*NN+pix];
            float p1=pred[(size_t)(b*3+1)*NN+pix];
            float p2=pred[(size_t)(b*3+2)*NN+pix];
            atomicAdd(&d_b4[base].x, wgt*p0);
            atomicAdd(&d_b4[base].y, wgt*p1);
            atomicAdd(&d_b4[base].z, wgt*p2);
        }
    }
    gridbar();

    // ---------- Ph5..14: bistochastization x10 ----------
    for(int it=0;it<10;it++){
        const float* src = (it&1)? d_nB : d_nA;
        float*       dst = (it&1)? d_nA : d_nB;
        for(int w=tid;w<BB*NN;w+=T){
            int b=(w>=NN); int a=w-(b?NN:0);
            if(a<d_Mcnt[b]){
                int base=b*NN+a;
                const int* nb=&d_nbr[(size_t)base*10];
                float v=src[base];
                float s=10.0f*v;
#pragma unroll
                for(int k=0;k<10;k++){
                    int id=nb[k];
                    if(id>=0) s+=src[b*NN+id];
                }
                dst[base]=sqrtf(v*d_cnt[base]/(s+1e-12f));
            }
        }
        gridbar();
    }

    // ---------- Ph15: prep (mm, diag, minv, edge weights, x0) ----------
    for(int w=tid;w<BB*NN;w+=T){
        int b=(w>=NN); int a=w-(b?NN:0);
        if(a<d_Mcnt[b]){
            int base=b*NN+a;
            const int* nb=&d_nbr[(size_t)base*10];
            float* ew=&d_ew[(size_t)base*10];
            float n=d_nA[base];
            float s=10.0f*n;
#pragma unroll
            for(int k=0;k<10;k++){
                int id=nb[k];
                if(id>=0){
                    float nk=d_nA[b*NN+id];
                    s+=nk;
                    ew[k]=200.0f*n*nk;
                }
            }
            float mm=n*s;
            float ws=d_ws[base];
            float dg=200.0f*(mm-10.0f*n*n)+ws;
            d_diag[base]=dg;
            d_minv[base]=1.0f/fmaxf(dg,1e-5f);
            float4 bb=d_b4[base];
            float inv=ws+1e-12f;
            d_x4[base]=make_float4(bb.x/inv,bb.y/inv,bb.z/inv,0.f);
        }
    }
    gridbar();

    // ---------- Ph16: CG init (r=b-A(x0), z, p, rz0) ----------
    {
        double acc[6]={0,0,0,0,0,0};
        for(int w=tid;w<BB*NN;w+=T){
            int b=(w>=NN); int a=w-(b?NN:0);
            if(a<d_Mcnt[b]){
                int base=b*NN+a;
                const int* nb=&d_nbr[(size_t)base*10];
                const float* ew=&d_ew[(size_t)base*10];
                float4 x=d_x4[base];
                float t0=0.f,t1=0.f,t2=0.f;
#pragma unroll
                for(int k=0;k<10;k++){
                    int id=nb[k];
                    if(id>=0){
                        float e=ew[k];
                        float4 q=d_x4[b*NN+id];
                        t0=fmaf(e,q.x,t0); t1=fmaf(e,q.y,t1); t2=fmaf(e,q.z,t2);
                    }
                }
                float dg=d_diag[base];
                float A0=dg*x.x-t0, A1=dg*x.y-t1, A2=dg*x.z-t2;
                float4 bb=d_b4[base];
                float r0=bb.x-A0, r1=bb.y-A1, r2=bb.z-A2;
                float mi=d_minv[base];
                float z0=mi*r0, z1=mi*r1, z2=mi*r2;
                d_r4[base]=make_float4(r0,r1,r2,0.f);
                d_z4[base]=make_float4(z0,z1,z2,0.f);
                d_p4[base]=make_float4(z0,z1,z2,0.f);
                int c=b*3;
                acc[c+0]+=(double)r0*z0; acc[c+1]+=(double)r1*z1; acc[c+2]+=(double)r2*z2;
            }
        }
        partout6(acc, d_rzpart + 0, G);
    }
    gridbar();

    // ---------- CG iterations ----------
    for(int it=0;it<12;it++){
        // A-phase: Ap = A(p), pAp partials
        {
            double acc[6]={0,0,0,0,0,0};
            for(int w=tid;w<BB*NN;w+=T){
                int b=(w>=NN); int a=w-(b?NN:0);
                if(a<d_Mcnt[b]){
                    int base=b*NN+a;
                    const int* nb=&d_nbr[(size_t)base*10];
                    const float* ew=&d_ew[(size_t)base*10];
                    float4 p=d_p4[base];
                    float t0=0.f,t1=0.f,t2=0.f;
#pragma unroll
                    for(int k=0;k<10;k++){
                        int id=nb[k];
                        if(id>=0){
                            float e=ew[k];
                            float4 q=d_p4[b*NN+id];
                            t0=fmaf(e,q.x,t0); t1=fmaf(e,q.y,t1); t2=fmaf(e,q.z,t2);
                        }
                    }
                    float dg=d_diag[base];
                    float A0=dg*p.x-t0, A1=dg*p.y-t1, A2=dg*p.z-t2;
                    d_Ap4[base]=make_float4(A0,A1,A2,0.f);
                    int c=b*3;
                    acc[c+0]+=(double)p.x*A0; acc[c+1]+=(double)p.y*A1; acc[c+2]+=(double)p.z*A2;
                }
            }
            partout6(acc, d_pappart + (size_t)it*6*G, G);
        }
        gridbar();

        // U1: alpha; x,r,z update; rz(it+1) partials
        {
            reduce6f(d_rzpart  + (size_t)it*6*G, G, s_rz);
            reduce6f(d_pappart + (size_t)it*6*G, G, s_pap);
            if(threadIdx.x<6) s_alpha[threadIdx.x]=s_rz[threadIdx.x]/(s_pap[threadIdx.x]+1e-12f);
            __syncthreads();
            double acc[6]={0,0,0,0,0,0};
            for(int w=tid;w<BB*NN;w+=T){
                int b=(w>=NN); int a=w-(b?NN:0);
                if(a<d_Mcnt[b]){
                    int base=b*NN+a;
                    int c=b*3;
                    float al0=s_alpha[c+0], al1=s_alpha[c+1], al2=s_alpha[c+2];
                    float4 p=d_p4[base], Ap=d_Ap4[base], x=d_x4[base], r=d_r4[base];
                    x.x+=al0*p.x; x.y+=al1*p.y; x.z+=al2*p.z;
                    r.x-=al0*Ap.x; r.y-=al1*Ap.y; r.z-=al2*Ap.z;
                    float mi=d_minv[base];
                    float z0=mi*r.x, z1=mi*r.y, z2=mi*r.z;
                    d_x4[base]=x; d_r4[base]=r;
                    d_z4[base]=make_float4(z0,z1,z2,0.f);
                    acc[c+0]+=(double)r.x*z0; acc[c+1]+=(double)r.y*z1; acc[c+2]+=(double)r.z*z2;
                }
            }
            partout6(acc, d_rzpart + (size_t)(it+1)*6*G, G);
        }
        gridbar();

        // U2: beta; p = z + beta*p
        {
            reduce6f(d_rzpart + (size_t)(it+1)*6*G, G, s_rzn);
            reduce6f(d_rzpart + (size_t)it*6*G,     G, s_rz);
            if(threadIdx.x<6) s_beta[threadIdx.x]=s_rzn[threadIdx.x]/(s_rz[threadIdx.x]+1e-12f);
            __syncthreads();
            for(int w=tid;w<BB*NN;w+=T){
                int b=(w>=NN); int a=w-(b?NN:0);
                if(a<d_Mcnt[b]){
                    int base=b*NN+a;
                    int c=b*3;
                    float4 z=d_z4[base], p=d_p4[base];
                    p.x=z.x+s_beta[c+0]*p.x;
                    p.y=z.y+s_beta[c+1]*p.y;
                    p.z=z.z+s_beta[c+2]*p.z;
                    d_p4[base]=p;
                }
            }
        }
        gridbar();
    }

    // ---------- output ----------
    {
        float cmax=s_cmax;
        for(int w=tid;w<BB*NN;w+=T){
            int b=(w>=NN); int pix=w-(b?NN:0);
            int a=d_pixa[w];
            float4 x=d_x4[b*NN+a];
            out[(size_t)(b*3+0)*NN+pix]=x.x;
            out[(size_t)(b*3+1)*NN+pix]=x.y;
            out[(size_t)(b*3+2)*NN+pix]=x.z;
            out[(size_t)BB*3*NN + w]=d_conf[w]/cmax;
        }
    }
}

// ------------------------- host -------------------------
extern "C" void kernel_launch(void* const* d_in, const int* in_sizes, int n_in,
                              void* d_out, int out_size){
    const float* image  =(const float*)d_in[0];
    const float* feature=(const float*)d_in[1];
    const float* pred   =(const float*)d_in[2];
    const float* w1 =(const float*)d_in[3];  const float* b1 =(const float*)d_in[4];
    const float* g1 =(const float*)d_in[5];  const float* be1=(const float*)d_in[6];
    const float* w2 =(const float*)d_in[7];  const float* b2 =(const float*)d_in[8];
    const float* g2 =(const float*)d_in[9];  const float* be2=(const float*)d_in[10];
    const float* wd1=(const float*)d_in[11]; const float* bd1=(const float*)d_in[12];
    const float* gd1=(const float*)d_in[13]; const float* bed1=(const float*)d_in[14];
    const float* wd2=(const float*)d_in[15]; const float* bd2=(const float*)d_in[16];
    const float* gd2=(const float*)d_in[17]; const float* bed2=(const float*)d_in[18];
    const float* wf =(const float*)d_in[19]; const float* bf =(const float*)d_in[20];
    float* out=(float*)d_out;

    void *p_mpart,*p_simg,*p_sfeat;
    void *p_inp,*p_x1,*p_x2,*p_dx1,*p_catb,*p_dx2,*p_dx2up,*p_conf;
    cudaGetSymbolAddress(&p_mpart,d_mpart);
    cudaGetSymbolAddress(&p_simg, d_simg);
    cudaGetSymbolAddress(&p_sfeat,d_sfeat);
    cudaGetSymbolAddress(&p_inp,  d_inp);
    cudaGetSymbolAddress(&p_x1,   d_x1);
    cudaGetSymbolAddress(&p_x2,   d_x2);
    cudaGetSymbolAddress(&p_dx1,  d_dx1);
    cudaGetSymbolAddress(&p_catb, d_catb);
    cudaGetSymbolAddress(&p_dx2,  d_dx2);
    cudaGetSymbolAddress(&p_dx2up,d_dx2up);
    cudaGetSymbolAddress(&p_conf, d_conf);
    float* mpart=(float*)p_mpart;

    // ---- norm_max scales ----
    k_maxpart<<<dim3(64,BB),256>>>(image,  3*NN, mpart);
    k_maxpart<<<dim3(64,BB),256>>>(feature,3*NN, mpart+BB*64);
    k_maxfin<<<BB,64>>>(mpart,        (float*)p_simg);
    k_maxfin<<<BB,64>>>(mpart+BB*64,  (float*)p_sfeat);

    // ---- CNN ----
    k_makeinp<<<(BB*3*NN+255)/256,256>>>(image,pred);

    dim3 cth(32,8);
    k_conv<6,16,4,2,true><<<dim3(8,24,BB),cth>>>(
        (const float*)p_inp,HH,WW,(float*)p_x1,H1,W1,w1,b1);
    { int HW=H1*W1;
      k_gnpart<<<dim3(NGB,2*BB),256>>>((const float*)p_x1,HW);
      k_gnfin<<<2*BB,32>>>(HW);
      k_gnapply<<<(BB*16*HW+255)/256,256>>>((float*)p_x1,HW,g1,be1); }

    k_conv<16,16,4,2,true><<<dim3(4,12,BB),cth>>>(
        (const float*)p_x1,H1,W1,(float*)p_x2,H2,W2,w2,b2);
    { int HW=H2*W2;
      k_gnpart<<<dim3(NGB,2*BB),256>>>((const float*)p_x2,HW);
      k_gnfin<<<2*BB,32>>>(HW);
      k_gnapply<<<(BB*16*HW+255)/256,256>>>((float*)p_x2,HW,g2,be2); }

    k_conv<16,16,3,1,false><<<dim3(4,12,BB),cth>>>(
        (const float*)p_x2,H2,W2,(float*)p_dx1,H2,W2,wd1,bd1);
    { int HW=H2*W2;
      k_gnpart<<<dim3(NGB,2*BB),256>>>((const float*)p_dx1,HW);
      k_gnfin<<<2*BB,32>>>(HW);
      k_gnapply<<<(BB*16*HW+255)/256,256>>>((float*)p_dx1,HW,gd1,bed1); }

    k_resize2x<<<(BB*16*H1*W1+255)/256,256>>>((const float*)p_dx1,H2,W2,(float*)p_catb,32,0);
    k_copy16<<<(BB*16*H1*W1+255)/256,256>>>();

    k_conv<32,16,3,1,false><<<dim3(8,24,BB),cth>>>(
        (const float*)p_catb,H1,W1,(float*)p_dx2,H1,W1,wd2,bd2);
    { int HW=H1*W1;
      k_gnpart<<<dim3(NGB,2*BB),256>>>((const float*)p_dx2,HW);
      k_gnfin<<<2*BB,32>>>(HW);
      k_gnapply<<<(BB*16*HW+255)/256,256>>>((float*)p_dx2,HW,gd2,bed2); }

    k_resize2x<<<(BB*16*NN+255)/256,256>>>((const float*)p_dx2,H1,W1,(float*)p_dx2up,16,0);

    k_conv<16,1,3,1,true><<<dim3(16,48,BB),cth>>>(
        (const float*)p_dx2up,HH,WW,(float*)p_conf,HH,WW,wf,bf);
    k_tanhconf<<<(BB*NN+255)/256,256>>>();

    // ---- persistent bilateral solver (everything else in ONE kernel) ----
    int sm=0; cudaDeviceGetAttribute(&sm, cudaDevAttrMultiProcessorCount, 0);
    int occ=0; cudaOccupancyMaxActiveBlocksPerMultiprocessor(&occ, k_solver, 512, 0);
    if(occ<1) occ=1;
    int G = sm*occ;
    if(G>MAXG) G=MAXG;
    G &= ~7;            // multiple of 8 for 2-level barrier
    if(G<8) G=8;
    k_solver<<<G,512>>>(feature,pred,out);
}

// round 7
// speedup vs baseline: 1.3683x; 1.0850x over previous
#include <cuda_runtime.h>
#include <math.h>

#define BB 2
#define HH 384
#define WW 512
#define NN (HH*WW)          // 196608 pixels
#define TT (1<<20)
#define TMASK (TT-1)
#define H1 192
#define W1 256
#define H2 96
#define W2 128
#define NGB 32
#define MAXG 1024

// ------------------------- CNN scratch -------------------------
__device__ float d_inp[BB*6*NN];
__device__ float d_x1[BB*16*H1*W1];
__device__ float d_x2[BB*16*H2*W2];
__device__ float d_dx1[BB*16*H2*W2];
__device__ float d_catb[BB*32*H1*W1];
__device__ float d_dx2[BB*16*H1*W1];
__device__ float d_dx2up[BB*16*NN];
__device__ float d_conf[BB*NN];

__device__ float  d_mpart[2*BB*64];
__device__ float  d_simg[BB];
__device__ float  d_sfeat[BB];

__device__ double d_gnp[2*BB*NGB*2];
__device__ float  d_gnmean[2*BB];
__device__ float  d_gnrstd[2*BB];

// ------------------------- solver scratch -------------------------
__device__ int    d_pixh[BB*NN];
__device__ int    d_pixa[BB*NN];
__device__ int    d_winner[BB*TT];
__device__ int    d_ctab[BB*TT*5];
__device__ int    d_cell2act[BB*TT];
__device__ int    d_actcell[BB*NN];
__device__ int    d_Mcnt[BB];
__device__ int    d_nbr[BB*NN*10];
__device__ float  d_ew[BB*NN*10];

__device__ float  d_cnt[BB*NN];
__device__ float  d_ws[BB*NN];
__device__ float  d_nA[BB*NN];
__device__ float  d_nB[BB*NN];
__device__ float  d_diag[BB*NN];
__device__ float  d_minv[BB*NN];
__device__ float4 d_b4[BB*NN];
__device__ float4 d_x4[BB*NN];
__device__ float4 d_r4[BB*NN];
__device__ float4 d_z4[BB*NN];
__device__ float4 d_p4[BB*NN];
__device__ float4 d_Ap4[BB*NN];

__device__ float  d_cpart[MAXG];

// per-iteration scalar accumulator slots (no partial arrays, no O(G^2) reads)
__device__ double d_rzS[13][6];
__device__ double d_papS[12][6];

// barrier state (self-cleaning across graph replays)
__device__ unsigned d_sub[8];
__device__ unsigned d_root;
__device__ volatile unsigned d_phase;

// ------------------------- helpers -------------------------
__device__ __forceinline__ int hash5i(int c0,int c1,int c2,int c3,int c4){
    unsigned s = (unsigned)c0*73856093u + (unsigned)c1*19349663u + (unsigned)c2*83492791u
               + (unsigned)c3*49979687u + (unsigned)c4*24036583u;
    return (int)(s & (unsigned)TMASK);
}

__device__ __forceinline__ void pix_coords(const float* __restrict__ feature,int b,int pix,int* c){
    float s = d_sfeat[b];
    float r  = (feature[(size_t)(b*3+0)*NN+pix]/s)*255.0f;
    float g  = (feature[(size_t)(b*3+1)*NN+pix]/s)*255.0f;
    float bl = (feature[(size_t)(b*3+2)*NN+pix]/s)*255.0f;
    int i = pix/WW, j = pix - i*WW;
    float Y = fmaf(bl,0.114f,    fmaf(g,0.587f,    r*0.299f));
    float U = fmaf(bl,0.5f,      fmaf(g,-0.331264f,r*(-0.168736f)))+128.0f;
    float V = fmaf(bl,-0.081312f,fmaf(g,-0.418688f,r*0.5f))+128.0f;
    c[0]=(int)floorf((float)j/7.0f);
    c[1]=(int)floorf((float)i/7.0f);
    c[2]=(int)floorf(Y*0.125f);
    c[3]=(int)floorf(U*0.5f);
    c[4]=(int)floorf(V*0.5f);
}

// grid-wide barrier: two-level arrival, phase-flag release.
__device__ __forceinline__ void gridbar(){
    __syncthreads();
    if(threadIdx.x==0){
        __threadfence();
        unsigned gen = d_phase;
        unsigned G = gridDim.x;
        unsigned g = blockIdx.x & 7u;
        unsigned gsz = (G - g + 7u) >> 3;
        unsigned t = atomicInc(&d_sub[g], gsz-1u);
        if(t == gsz-1u){
            unsigned r = atomicInc(&d_root, 7u);
            if(r == 7u){
                __threadfence();
                d_phase = gen+1u;
            }
        }
        while(d_phase == gen){}
    }
    __syncthreads();
    __threadfence();   // acquire
}

// block-reduce 6 doubles -> single atomicAdd per channel into slot[6]
__device__ __forceinline__ void slotAdd6(double* acc, double* slot){
    __shared__ double s_red[16][6];
    int wp=threadIdx.x>>5, ln=threadIdx.x&31;
#pragma unroll
    for(int c=0;c<6;c++){
        double v=acc[c];
        for(int off=16;off;off>>=1) v+=__shfl_down_sync(0xffffffffu,v,off);
        if(ln==0) s_red[wp][c]=v;
    }
    __syncthreads();
    if(threadIdx.x<6){
        double s=0; int nw=blockDim.x>>5;
        for(int w=0;w<nw;w++) s+=s_red[w][threadIdx.x];
        atomicAdd(&slot[threadIdx.x], s);
    }
    __syncthreads();
}

// ------------------------- CNN kernels (unchanged, known-good) -------------------------
__global__ void k_maxpart(const float* __restrict__ x, int perBatch, float* dst){
    int b = blockIdx.y;
    const float* p = x + (size_t)b*perBatch;
    float m = -1e30f;
    for(int i=blockIdx.x*256+threadIdx.x;i<perBatch;i+=gridDim.x*256)
        m = fmaxf(m, p[i]);
    __shared__ float sh[256];
    sh[threadIdx.x]=m; __syncthreads();
    for(int s=128;s>0;s>>=1){
        if(threadIdx.x<s) sh[threadIdx.x]=fmaxf(sh[threadIdx.x],sh[threadIdx.x+s]);
        __syncthreads();
    }
    if(threadIdx.x==0) dst[b*gridDim.x+blockIdx.x]=sh[0];
}

__global__ void k_maxfin(const float* part, float* sdst){
    int b = blockIdx.x;
    __shared__ float sh[64];
    sh[threadIdx.x]=part[b*64+threadIdx.x]; __syncthreads();
    for(int s=32;s>0;s>>=1){
        if(threadIdx.x<s) sh[threadIdx.x]=fmaxf(sh[threadIdx.x],sh[threadIdx.x+s]);
        __syncthreads();
    }
    if(threadIdx.x==0) sdst[b]=fminf(fmaxf(sh[0],1e-5f),1.0f);
}

__global__ void k_makeinp(const float* __restrict__ image, const float* __restrict__ pred){
    int i = blockIdx.x*256+threadIdx.x;
    if(i>=BB*3*NN) return;
    int b = i/(3*NN);
    int r = i - b*3*NN;
    d_inp[b*6*NN + r]        = image[i] / d_simg[b];
    d_inp[b*6*NN + 3*NN + r] = pred[i];
}

template<int IC,int OC,int K,int S,bool EDGE>
__global__ void k_conv(const float* __restrict__ in,int IH,int IW,
                       float* __restrict__ out,int OH,int OW,
                       const float* __restrict__ wt,const float* __restrict__ bs){
    __shared__ float sw[OC*IC*K*K];
    int tid = threadIdx.y*32+threadIdx.x;
    for(int i=tid;i<OC*IC*K*K;i+=256){
        int oc = i/(IC*K*K);
        int rest = i - oc*IC*K*K;
        sw[rest*OC+oc]=wt[i];
    }
    __syncthreads();
    int ox = blockIdx.x*32+threadIdx.x;
    int oy = blockIdx.y*8+threadIdx.y;
    int b  = blockIdx.z;
    if(ox>=OW||oy>=OH) return;
    float acc[OC];
#pragma unroll
    for(int oc=0;oc<OC;oc++) acc[oc]=bs[oc];
    for(int ic=0;ic<IC;ic++){
        const float* ip = in + ((size_t)(b*IC+ic))*IH*IW;
#pragma unroll
        for(int ky=0;ky<K;ky++){
            int iy = oy*S - 1 + ky;
            if(EDGE) iy = min(max(iy,0),IH-1);
            else if(iy<0||iy>=IH) continue;
#pragma unroll
            for(int kx=0;kx<K;kx++){
                int ix = ox*S - 1 + kx;
                if(EDGE) ix = min(max(ix,0),IW-1);
                else if(ix<0||ix>=IW) continue;
                float v = ip[iy*IW+ix];
                const float* w = &sw[((ic*K+ky)*K+kx)*OC];
#pragma unroll
                for(int oc=0;oc<OC;oc++)
                    acc[oc]=fmaf(v,w[oc],acc[oc]);
            }
        }
    }
#pragma unroll
    for(int oc=0;oc<OC;oc++)
        out[((size_t)(b*OC+oc)*OH+oy)*OW+ox]=acc[oc];
}

__global__ void k_gnpart(const float* __restrict__ raw,int HW){
    int grp = blockIdx.y;
    int b = grp>>1, g = grp&1;
    const float* base = raw + (size_t)(b*16+g*8)*HW;
    int cnt = 8*HW;
    double s=0,q=0;
    for(int i=blockIdx.x*256+threadIdx.x;i<cnt;i+=gridDim.x*256){
        double v = base[i]; s+=v; q+=v*v;
    }
    __shared__ double sh[256],sh2[256];
    sh[threadIdx.x]=s; sh2[threadIdx.x]=q; __syncthreads();
    for(int st=128;st>0;st>>=1){
        if(threadIdx.x<st){sh[threadIdx.x]+=sh[threadIdx.x+st];sh2[threadIdx.x]+=sh2[threadIdx.x+st];}
        __syncthreads();
    }
    if(threadIdx.x==0){
        d_gnp[(grp*NGB+blockIdx.x)*2]=sh[0];
        d_gnp[(grp*NGB+blockIdx.x)*2+1]=sh2[0];
    }
}

__global__ void k_gnfin(int HW){
    int grp = blockIdx.x;
    double s=0,q=0;
    for(int i=threadIdx.x;i<NGB;i+=32){
        s+=d_gnp[(grp*NGB+i)*2];
        q+=d_gnp[(grp*NGB+i)*2+1];
    }
    for(int off=16;off;off>>=1){
        s+=__shfl_down_sync(0xffffffffu,s,off);
        q+=__shfl_down_sync(0xffffffffu,q,off);
    }
    if(threadIdx.x==0){
        double n = 8.0*HW;
        double mean = s/n;
        double var  = q/n - mean*mean;
        d_gnmean[grp]=(float)mean;
        d_gnrstd[grp]=(float)(1.0/sqrt(var+1e-5));
    }
}

__global__ void k_gnapply(float* __restrict__ x,int HW,
                          const float* __restrict__ gam,const float* __restrict__ bet){
    int i = blockIdx.x*256+threadIdx.x;
    if(i>=BB*16*HW) return;
    int c = (i/HW)&15;
    int b = i/(16*HW);
    int grp = b*2 + (c>>3);
    float v = (x[i]-d_gnmean[grp])*d_gnrstd[grp]*gam[c]+bet[c];
    x[i]=fmaxf(v,0.0f);
}

__global__ void k_resize2x(const float* __restrict__ in,int IH,int IW,
                           float* __restrict__ out,int outCtot,int chOff){
    int OH=IH*2, OW=IW*2;
    int total=BB*16*OH*OW;
    int i=blockIdx.x*256+threadIdx.x;
    if(i>=total) return;
    int ox=i%OW; int rest=i/OW;
    int oy=rest%OH; rest/=OH;
    int c=rest%16; int b=rest/16;
    float cy=oy*0.5f-0.25f, cx=ox*0.5f-0.25f;
    int y0=(int)floorf(cy); float fy=cy-(float)y0;
    int x0=(int)floorf(cx); float fx=cx-(float)x0;
    int y1=min(y0+1,IH-1), x1=min(x0+1,IW-1);
    y0=max(y0,0); x0=max(x0,0);
    const float* ip = in + ((size_t)(b*16+c))*IH*IW;
    float v00=ip[y0*IW+x0], v01=ip[y0*IW+x1];
    float v10=ip[y1*IW+x0], v11=ip[y1*IW+x1];
    float top=v00+fx*(v01-v00);
    float bot=v10+fx*(v11-v10);
    out[((size_t)(b*outCtot+chOff+c)*OH+oy)*OW+ox]=top+fy*(bot-top);
}

__global__ void k_copy16(){
    int i=blockIdx.x*256+threadIdx.x;
    int HW=H1*W1;
    if(i>=BB*16*HW) return;
    int p=i%HW; int c=(i/HW)&15; int b=i/(16*HW);
    d_catb[((size_t)(b*32+16+c))*HW+p]=d_x1[((size_t)(b*16+c))*HW+p];
}

__global__ void k_tanhconf(){
    int i=blockIdx.x*256+threadIdx.x;
    if(i>=BB*NN) return;
    d_conf[i]=0.5f*(tanhf(d_conf[i])+1.0f);
}

// ------------------------- persistent bilateral solver -------------------------
__global__ void __launch_bounds__(512) k_solver(const float* __restrict__ feature,
                                               const float* __restrict__ pred,
                                               float* __restrict__ out){
    const int T   = blockDim.x*gridDim.x;
    const int tid = blockIdx.x*blockDim.x + threadIdx.x;
    const int G   = gridDim.x;
    const int wp  = threadIdx.x>>5, ln = threadIdx.x&31;

    __shared__ float s_w[16];
    __shared__ float s_cmax;
    __shared__ float s_alpha[6], s_beta[6];

    // ---------- Ph0: clears + conf-max partial ----------
    for(int i=tid;i<BB*TT;i+=T) d_winner[i]=-1;
    if(tid<BB) d_Mcnt[tid]=0;
    if(tid<13*6) ((double*)d_rzS)[tid]=0.0;
    if(tid>=64 && tid<64+12*6) ((double*)d_papS)[tid-64]=0.0;
    for(int i=tid;i<BB*NN;i+=T){
        d_cnt[i]=0.f; d_ws[i]=0.f;
        d_b4[i]=make_float4(0.f,0.f,0.f,0.f);
    }
    {
        float cm=-1e30f;
        for(int i=tid;i<BB*NN;i+=T) cm=fmaxf(cm,d_conf[i]);
        for(int off=16;off;off>>=1) cm=fmaxf(cm,__shfl_down_sync(0xffffffffu,cm,off));
        if(ln==0) s_w[wp]=cm;
        __syncthreads();
        if(threadIdx.x==0){
            float m=-1e30f; int nw=blockDim.x>>5;
            for(int w=0;w<nw;w++) m=fmaxf(m,s_w[w]);
            d_cpart[blockIdx.x]=m;
        }
        __syncthreads();
    }
    gridbar();

    // ---------- Ph1: hash ----------
    for(int w=tid;w<BB*NN;w+=T){
        int b = (w>=NN); int pix = w - (b? NN:0);
        int c[5]; pix_coords(feature,b,pix,c);
        int h=hash5i(c[0],c[1],c[2],c[3],c[4]);
        d_pixh[w]=h;
        atomicMax(&d_winner[b*TT+h],pix);
    }
    gridbar();

    // ---------- Ph2: ctab (winner writes its coords) ----------
    for(int w=tid;w<BB*NN;w+=T){
        int b = (w>=NN); int pix = w - (b? NN:0);
        int h = d_pixh[w];
        if(d_winner[b*TT+h]==pix){
            int c[5]; pix_coords(feature,b,pix,c);
            int* t=&d_ctab[(b*TT+h)*5];
            t[0]=c[0];t[1]=c[1];t[2]=c[2];t[3]=c[3];t[4]=c[4];
        }
    }
    gridbar();

    // ---------- Ph3: compact (warp-aggregated atomics) ----------
    for(int i0=0;i0<BB*TT;i0+=T){
        int i=i0+tid;
        bool on = (i<BB*TT) && (d_winner[i]>=0);
        unsigned m=__ballot_sync(0xffffffffu,on);
        if(m){
            int leader=__ffs(m)-1;
            int wbase = i0 + blockIdx.x*blockDim.x + (threadIdx.x & ~31);
            int bb_ = (wbase + leader)>>20;
            int base=0;
            if(ln==leader) base=atomicAdd(&d_Mcnt[bb_],__popc(m));
            base=__shfl_sync(0xffffffffu,base,leader);
            if(on){
                int a=base+__popc(m & ((1u<<ln)-1u));
                d_actcell[bb_*NN+a]=i&TMASK;
                d_cell2act[i]=a;
            }
        }
    }
    gridbar();

    // ---------- Ph4: neighbor build + splat ----------
    for(int w=tid;w<BB*NN;w+=T){
        int b=(w>=NN); int a=w-(b?NN:0);
        if(a<d_Mcnt[b]){
            int cell=d_actcell[b*NN+a];
            const int* me=&d_ctab[(b*TT+cell)*5];
            int cc[5]={me[0],me[1],me[2],me[3],me[4]};
            int* nb=&d_nbr[(size_t)(b*NN+a)*10];
            int k=0;
#pragma unroll
            for(int d=0;d<5;d++){
#pragma unroll
                for(int o=0;o<2;o++){
                    int nc[5]={cc[0],cc[1],cc[2],cc[3],cc[4]};
                    nc[d]+= o?1:-1;
                    int nh=hash5i(nc[0],nc[1],nc[2],nc[3],nc[4]);
                    int res=-1;
                    if(d_winner[b*TT+nh]>=0){
                        const int* t=&d_ctab[(b*TT+nh)*5];
                        if(t[0]==nc[0]&&t[1]==nc[1]&&t[2]==nc[2]&&t[3]==nc[3]&&t[4]==nc[4])
                            res=d_cell2act[b*TT+nh];
                    }
                    nb[k++]=res;
                }
            }
            d_nA[b*NN+a]=1.0f;
        }
    }
    // conf max (reduce partials) then splat
    if(wp==0){
        float m=-1e30f;
        for(int i=ln;i<G;i+=32) m=fmaxf(m,d_cpart[i]);
        for(int off=16;off;off>>=1) m=fmaxf(m,__shfl_down_sync(0xffffffffu,m,off));
        if(ln==0) s_cmax=fmaxf(m,1e-5f);
    }
    __syncthreads();
    {
        float cmax=s_cmax;
        for(int w=tid;w<BB*NN;w+=T){
            int b=(w>=NN); int pix=w-(b?NN:0);
            int h=d_pixh[w];
            int a=d_cell2act[b*TT+h];
            d_pixa[w]=a;
            int base=b*NN+a;
            float wgt=d_conf[w]/cmax;
            atomicAdd(&d_cnt[base],1.0f);
            atomicAdd(&d_ws[base],wgt);
            float p0=pred[(size_t)(b*3+0)*NN+pix];
            float p1=pred[(size_t)(b*3+1)*NN+pix];
            float p2=pred[(size_t)(b*3+2)*NN+pix];
            atomicAdd(&d_b4[base].x, wgt*p0);
            atomicAdd(&d_b4[base].y, wgt*p1);
            atomicAdd(&d_b4[base].z, wgt*p2);
        }
    }
    gridbar();

    // ---------- Ph5..14: bistochastization x10 ----------
    for(int it=0;it<10;it++){
        const float* src = (it&1)? d_nB : d_nA;
        float*       dst = (it&1)? d_nA : d_nB;
        for(int w=tid;w<BB*NN;w+=T){
            int b=(w>=NN); int a=w-(b?NN:0);
            if(a<d_Mcnt[b]){
                int base=b*NN+a;
                const int* nb=&d_nbr[(size_t)base*10];
                float v=src[base];
                float s=10.0f*v;
#pragma unroll
                for(int k=0;k<10;k++){
                    int id=nb[k];
                    if(id>=0) s+=src[b*NN+id];
                }
                dst[base]=sqrtf(v*d_cnt[base]/(s+1e-12f));
            }
        }
        gridbar();
    }

    // ---------- Ph15: prep (mm, diag, minv, edge weights, x0) ----------
    for(int w=tid;w<BB*NN;w+=T){
        int b=(w>=NN); int a=w-(b?NN:0);
        if(a<d_Mcnt[b]){
            int base=b*NN+a;
            const int* nb=&d_nbr[(size_t)base*10];
            float* ew=&d_ew[(size_t)base*10];
            float n=d_nA[base];
            float s=10.0f*n;
#pragma unroll
            for(int k=0;k<10;k++){
                int id=nb[k];
                if(id>=0){
                    float nk=d_nA[b*NN+id];
                    s+=nk;
                    ew[k]=200.0f*n*nk;
                }
            }
            float mm=n*s;
            float ws=d_ws[base];
            float dg=200.0f*(mm-10.0f*n*n)+ws;
            d_diag[base]=dg;
            d_minv[base]=1.0f/fmaxf(dg,1e-5f);
            float4 bb=d_b4[base];
            float inv=ws+1e-12f;
            d_x4[base]=make_float4(bb.x/inv,bb.y/inv,bb.z/inv,0.f);
        }
    }
    gridbar();

    // ---------- Ph16: CG init (r=b-A(x0), z, p, rz0) ----------
    {
        double acc[6]={0,0,0,0,0,0};
        for(int w=tid;w<BB*NN;w+=T){
            int b=(w>=NN); int a=w-(b?NN:0);
            if(a<d_Mcnt[b]){
                int base=b*NN+a;
                const int* nb=&d_nbr[(size_t)base*10];
                const float* ew=&d_ew[(size_t)base*10];
                float4 x=d_x4[base];
                float t0=0.f,t1=0.f,t2=0.f;
#pragma unroll
                for(int k=0;k<10;k++){
                    int id=nb[k];
                    if(id>=0){
                        float e=ew[k];
                        float4 q=d_x4[b*NN+id];
                        t0=fmaf(e,q.x,t0); t1=fmaf(e,q.y,t1); t2=fmaf(e,q.z,t2);
                    }
                }
                float dg=d_diag[base];
                float A0=dg*x.x-t0, A1=dg*x.y-t1, A2=dg*x.z-t2;
                float4 bb=d_b4[base];
                float r0=bb.x-A0, r1=bb.y-A1, r2=bb.z-A2;
                float mi=d_minv[base];
                float z0=mi*r0, z1=mi*r1, z2=mi*r2;
                d_r4[base]=make_float4(r0,r1,r2,0.f);
                d_z4[base]=make_float4(z0,z1,z2,0.f);
                d_p4[base]=make_float4(z0,z1,z2,0.f);
                int c=b*3;
                acc[c+0]+=(double)r0*z0; acc[c+1]+=(double)r1*z1; acc[c+2]+=(double)r2*z2;
            }
        }
        slotAdd6(acc, d_rzS[0]);
    }
    gridbar();

    // ---------- CG iterations ----------
    for(int it=0;it<12;it++){
        // A-phase: Ap = A(p), pAp slot
        {
            double acc[6]={0,0,0,0,0,0};
            for(int w=tid;w<BB*NN;w+=T){
                int b=(w>=NN); int a=w-(b?NN:0);
                if(a<d_Mcnt[b]){
                    int base=b*NN+a;
                    const int* nb=&d_nbr[(size_t)base*10];
                    const float* ew=&d_ew[(size_t)base*10];
                    float4 p=d_p4[base];
                    float t0=0.f,t1=0.f,t2=0.f;
#pragma unroll
                    for(int k=0;k<10;k++){
                        int id=nb[k];
                        if(id>=0){
                            float e=ew[k];
                            float4 q=d_p4[b*NN+id];
                            t0=fmaf(e,q.x,t0); t1=fmaf(e,q.y,t1); t2=fmaf(e,q.z,t2);
                        }
                    }
                    float dg=d_diag[base];
                    float A0=dg*p.x-t0, A1=dg*p.y-t1, A2=dg*p.z-t2;
                    d_Ap4[base]=make_float4(A0,A1,A2,0.f);
                    int c=b*3;
                    acc[c+0]+=(double)p.x*A0; acc[c+1]+=(double)p.y*A1; acc[c+2]+=(double)p.z*A2;
                }
            }
            slotAdd6(acc, d_papS[it]);
        }
        gridbar();

        // U1: alpha; x,r,z update; rz(it+1) slot
        {
            if(threadIdx.x<6)
                s_alpha[threadIdx.x]=(float)d_rzS[it][threadIdx.x]/((float)d_papS[it][threadIdx.x]+1e-12f);
            __syncthreads();
            double acc[6]={0,0,0,0,0,0};
            for(int w=tid;w<BB*NN;w+=T){
                int b=(w>=NN); int a=w-(b?NN:0);
                if(a<d_Mcnt[b]){
                    int base=b*NN+a;
                    int c=b*3;
                    float al0=s_alpha[c+0], al1=s_alpha[c+1], al2=s_alpha[c+2];
                    float4 p=d_p4[base], Ap=d_Ap4[base], x=d_x4[base], r=d_r4[base];
                    x.x+=al0*p.x; x.y+=al1*p.y; x.z+=al2*p.z;
                    r.x-=al0*Ap.x; r.y-=al1*Ap.y; r.z-=al2*Ap.z;
                    float mi=d_minv[base];
                    float z0=mi*r.x, z1=mi*r.y, z2=mi*r.z;
                    d_x4[base]=x; d_r4[base]=r;
                    d_z4[base]=make_float4(z0,z1,z2,0.f);
                    acc[c+0]+=(double)r.x*z0; acc[c+1]+=(double)r.y*z1; acc[c+2]+=(double)r.z*z2;
                }
            }
            slotAdd6(acc, d_rzS[it+1]);
        }
        gridbar();

        // U2: beta; p = z + beta*p
        {
            if(threadIdx.x<6)
                s_beta[threadIdx.x]=(float)d_rzS[it+1][threadIdx.x]/((float)d_rzS[it][threadIdx.x]+1e-12f);
            __syncthreads();
            for(int w=tid;w<BB*NN;w+=T){
                int b=(w>=NN); int a=w-(b?NN:0);
                if(a<d_Mcnt[b]){
                    int base=b*NN+a;
                    int c=b*3;
                    float4 z=d_z4[base], p=d_p4[base];
                    p.x=z.x+s_beta[c+0]*p.x;
                    p.y=z.y+s_beta[c+1]*p.y;
                    p.z=z.z+s_beta[c+2]*p.z;
                    d_p4[base]=p;
                }
            }
        }
        gridbar();
    }

    // ---------- output ----------
    {
        float cmax=s_cmax;
        for(int w=tid;w<BB*NN;w+=T){
            int b=(w>=NN); int pix=w-(b?NN:0);
            int a=d_pixa[w];
            float4 x=d_x4[b*NN+a];
            out[(size_t)(b*3+0)*NN+pix]=x.x;
            out[(size_t)(b*3+1)*NN+pix]=x.y;
            out[(size_t)(b*3+2)*NN+pix]=x.z;
            out[(size_t)BB*3*NN + w]=d_conf[w]/cmax;
        }
    }
}

// ------------------------- host -------------------------
extern "C" void kernel_launch(void* const* d_in, const int* in_sizes, int n_in,
                              void* d_out, int out_size){
    const float* image  =(const float*)d_in[0];
    const float* feature=(const float*)d_in[1];
    const float* pred   =(const float*)d_in[2];
    const float* w1 =(const float*)d_in[3];  const float* b1 =(const float*)d_in[4];
    const float* g1 =(const float*)d_in[5];  const float* be1=(const float*)d_in[6];
    const float* w2 =(const float*)d_in[7];  const float* b2 =(const float*)d_in[8];
    const float* g2 =(const float*)d_in[9];  const float* be2=(const float*)d_in[10];
    const float* wd1=(const float*)d_in[11]; const float* bd1=(const float*)d_in[12];
    const float* gd1=(const float*)d_in[13]; const float* bed1=(const float*)d_in[14];
    const float* wd2=(const float*)d_in[15]; const float* bd2=(const float*)d_in[16];
    const float* gd2=(const float*)d_in[17]; const float* bed2=(const float*)d_in[18];
    const float* wf =(const float*)d_in[19]; const float* bf =(const float*)d_in[20];
    float* out=(float*)d_out;

    void *p_mpart,*p_simg,*p_sfeat;
    void *p_inp,*p_x1,*p_x2,*p_dx1,*p_catb,*p_dx2,*p_dx2up,*p_conf;
    cudaGetSymbolAddress(&p_mpart,d_mpart);
    cudaGetSymbolAddress(&p_simg, d_simg);
    cudaGetSymbolAddress(&p_sfeat,d_sfeat);
    cudaGetSymbolAddress(&p_inp,  d_inp);
    cudaGetSymbolAddress(&p_x1,   d_x1);
    cudaGetSymbolAddress(&p_x2,   d_x2);
    cudaGetSymbolAddress(&p_dx1,  d_dx1);
    cudaGetSymbolAddress(&p_catb, d_catb);
    cudaGetSymbolAddress(&p_dx2,  d_dx2);
    cudaGetSymbolAddress(&p_dx2up,d_dx2up);
    cudaGetSymbolAddress(&p_conf, d_conf);
    float* mpart=(float*)p_mpart;

    // ---- norm_max scales ----
    k_maxpart<<<dim3(64,BB),256>>>(image,  3*NN, mpart);
    k_maxpart<<<dim3(64,BB),256>>>(feature,3*NN, mpart+BB*64);
    k_maxfin<<<BB,64>>>(mpart,        (float*)p_simg);
    k_maxfin<<<BB,64>>>(mpart+BB*64,  (float*)p_sfeat);

    // ---- CNN ----
    k_makeinp<<<(BB*3*NN+255)/256,256>>>(image,pred);

    dim3 cth(32,8);
    k_conv<6,16,4,2,true><<<dim3(8,24,BB),cth>>>(
        (const float*)p_inp,HH,WW,(float*)p_x1,H1,W1,w1,b1);
    { int HW=H1*W1;
      k_gnpart<<<dim3(NGB,2*BB),256>>>((const float*)p_x1,HW);
      k_gnfin<<<2*BB,32>>>(HW);
      k_gnapply<<<(BB*16*HW+255)/256,256>>>((float*)p_x1,HW,g1,be1); }

    k_conv<16,16,4,2,true><<<dim3(4,12,BB),cth>>>(
        (const float*)p_x1,H1,W1,(float*)p_x2,H2,W2,w2,b2);
    { int HW=H2*W2;
      k_gnpart<<<dim3(NGB,2*BB),256>>>((const float*)p_x2,HW);
      k_gnfin<<<2*BB,32>>>(HW);
      k_gnapply<<<(BB*16*HW+255)/256,256>>>((float*)p_x2,HW,g2,be2); }

    k_conv<16,16,3,1,false><<<dim3(4,12,BB),cth>>>(
        (const float*)p_x2,H2,W2,(float*)p_dx1,H2,W2,wd1,bd1);
    { int HW=H2*W2;
      k_gnpart<<<dim3(NGB,2*BB),256>>>((const float*)p_dx1,HW);
      k_gnfin<<<2*BB,32>>>(HW);
      k_gnapply<<<(BB*16*HW+255)/256,256>>>((float*)p_dx1,HW,gd1,bed1); }

    k_resize2x<<<(BB*16*H1*W1+255)/256,256>>>((const float*)p_dx1,H2,W2,(float*)p_catb,32,0);
    k_copy16<<<(BB*16*H1*W1+255)/256,256>>>();

    k_conv<32,16,3,1,false><<<dim3(8,24,BB),cth>>>(
        (const float*)p_catb,H1,W1,(float*)p_dx2,H1,W1,wd2,bd2);
    { int HW=H1*W1;
      k_gnpart<<<dim3(NGB,2*BB),256>>>((const float*)p_dx2,HW);
      k_gnfin<<<2*BB,32>>>(HW);
      k_gnapply<<<(BB*16*HW+255)/256,256>>>((float*)p_dx2,HW,gd2,bed2); }

    k_resize2x<<<(BB*16*NN+255)/256,256>>>((const float*)p_dx2,H1,W1,(float*)p_dx2up,16,0);

    k_conv<16,1,3,1,true><<<dim3(16,48,BB),cth>>>(
        (const float*)p_dx2up,HH,WW,(float*)p_conf,HH,WW,wf,bf);
    k_tanhconf<<<(BB*NN+255)/256,256>>>();

    // ---- persistent bilateral solver (everything else in ONE kernel) ----
    int sm=0; cudaDeviceGetAttribute(&sm, cudaDevAttrMultiProcessorCount, 0);
    int occ=0; cudaOccupancyMaxActiveBlocksPerMultiprocessor(&occ, k_solver, 512, 0);
    if(occ<1) occ=1;
    int G = sm*occ;
    if(G>MAXG) G=MAXG;
    G &= ~7;            // multiple of 8 for 2-level barrier
    if(G<8) G=8;
    k_solver<<<G,512>>>(feature,pred,out);
}

// round 8
// speedup vs baseline: 1.6005x; 1.1697x over previous
#include <cuda_runtime.h>
#include <math.h>

#define BB 2
#define HH 384
#define WW 512
#define NN (HH*WW)          // 196608 pixels
#define TT (1<<20)
#define TMASK (TT-1)
#define H1 192
#define W1 256
#define H2 96
#define W2 128
#define MAXG 1024

// ------------------------- device scratch -------------------------
__device__ float d_x1[BB*16*H1*W1];
__device__ float d_x2[BB*16*H2*W2];
__device__ float d_dx1[BB*16*H2*W2];
__device__ float d_catb[BB*32*H1*W1];
__device__ float d_dx2[BB*16*H1*W1];
__device__ float d_dx2up[BB*16*NN];
__device__ float d_conf[BB*NN];

__device__ unsigned d_simgU[BB];
__device__ unsigned d_sfeatU[BB];
__device__ unsigned d_cmaxU;
__device__ double   d_gnS[4][8];     // [layer][grp*2 + {sum,sq}]

__device__ int       d_pixh[BB*NN];
__device__ int       d_pixa[BB*NN];
__device__ long long d_pixkey[BB*NN];
__device__ int       d_winner[BB*TT];
__device__ unsigned long long d_ctabP[BB*TT];
__device__ int       d_cell2act[BB*TT];
__device__ int       d_actcell[BB*NN];
__device__ int       d_Mcnt[BB];
__device__ int       d_nbr[BB*NN*10];
__device__ float     d_ew[BB*NN*10];

__device__ float  d_cnt[BB*NN];
__device__ float  d_ws[BB*NN];
__device__ float  d_nA[BB*NN];
__device__ float  d_nB[BB*NN];
__device__ float  d_diag[BB*NN];
__device__ float  d_minv[BB*NN];
__device__ float4 d_b4[BB*NN];
__device__ float4 d_x4[BB*NN];
__device__ float4 d_r4[BB*NN];
__device__ float4 d_z4[BB*NN];
__device__ float4 d_p4[BB*NN];
__device__ float4 d_Ap4[BB*NN];

__device__ double d_rzS[13][8];
__device__ double d_papS[12][8];

// barrier state (self-cleaning across graph replays)
__device__ unsigned d_sub[8];
__device__ unsigned d_root;
__device__ volatile unsigned d_phase;

// ------------------------- helpers -------------------------
__device__ __forceinline__ void gridbar(){
    __syncthreads();
    if(threadIdx.x==0){
        __threadfence();
        unsigned gen = d_phase;
        unsigned G = gridDim.x;
        unsigned g = blockIdx.x & 7u;
        unsigned gsz = (G - g + 7u) >> 3;
        unsigned t = atomicInc(&d_sub[g], gsz-1u);
        if(t == gsz-1u){
            unsigned r = atomicInc(&d_root, 7u);
            if(r == 7u){
                __threadfence();
                d_phase = gen+1u;
            }
        }
        while(d_phase == gen){}
    }
    __syncthreads();
    __threadfence();
}

__device__ __forceinline__ void slotAdd8(const double* acc, double* slot){
    __shared__ double s8[16][8];
    int wp=threadIdx.x>>5, ln=threadIdx.x&31;
#pragma unroll
    for(int c=0;c<8;c++){
        double v=acc[c];
        for(int off=16;off;off>>=1) v+=__shfl_down_sync(0xffffffffu,v,off);
        if(ln==0) s8[wp][c]=v;
    }
    __syncthreads();
    if(threadIdx.x<8){
        double s=0; int nw=blockDim.x>>5;
        for(int w=0;w<nw;w++) s+=s8[w][threadIdx.x];
        atomicAdd(&slot[threadIdx.x], s);
    }
    __syncthreads();
}

__device__ __forceinline__ void blockMaxAtomic(float v, unsigned* slot){
    __shared__ float sm[16];
    int wp=threadIdx.x>>5, ln=threadIdx.x&31;
    for(int off=16;off;off>>=1) v=fmaxf(v,__shfl_down_sync(0xffffffffu,v,off));
    if(ln==0) sm[wp]=v;
    __syncthreads();
    if(threadIdx.x==0){
        float m=0.f; int nw=blockDim.x>>5;
        for(int w=0;w<nw;w++) m=fmaxf(m,sm[w]);
        atomicMax(slot, __float_as_uint(m));
    }
    __syncthreads();
}

// GN prep: mean/rstd for 4 groups + gamma/beta into s_misc at 'off'
__device__ __forceinline__ void prep_gn(int layer,int HW,const float* __restrict__ gam,
                                        const float* __restrict__ bet,float* s_misc,int off){
    if(threadIdx.x<4){
        double s=d_gnS[layer][threadIdx.x*2], q=d_gnS[layer][threadIdx.x*2+1];
        double n=8.0*(double)HW;
        double mean=s/n, var=q/n-mean*mean;
        s_misc[off+threadIdx.x]=(float)mean;
        s_misc[off+4+threadIdx.x]=(float)(1.0/sqrt(var+1e-5));
    }
    if(threadIdx.x>=32&&threadIdx.x<48) s_misc[off+8+(threadIdx.x-32)]=gam[threadIdx.x-32];
    if(threadIdx.x>=64&&threadIdx.x<80) s_misc[off+24+(threadIdx.x-64)]=bet[threadIdx.x-64];
}

__device__ __forceinline__ float gn_apply(float raw,int b,int c,const float* s_misc,int off){
    int grp=b*2+(c>>3);
    float v=(raw-s_misc[off+grp])*s_misc[off+4+grp]*s_misc[off+8+c]+s_misc[off+24+c];
    return fmaxf(v,0.0f);
}

// input read: INMODE 0=plain, 1=conv1 (image/simg | pred), 2=GN+relu from 'in'
template<int INMODE,int IC>
__device__ __forceinline__ float rd(const float* __restrict__ in,
                                    const float* __restrict__ image,
                                    const float* __restrict__ pred,
                                    const float* s_misc,int b,int c,int iy,int ix,int IH,int IW){
    if(INMODE==1){
        size_t off=((size_t)(b*3+(c%3))*IH+iy)*IW+ix;
        return (c<3)? image[off]/s_misc[80+b] : pred[off];
    }
    float raw=in[((size_t)(b*IC+c)*IH+iy)*IW+ix];
    if(INMODE==2) return gn_apply(raw,b,c,s_misc,0);
    return raw;
}

// conv phase: 2-pixel register blocking, optional GN-in (INMODE=2), optional GN-out stats
template<int IC,int OC,int K,int S,bool EDGE,int INMODE,int GNIN,int GNOUT>
__device__ void conv_ph(const float* __restrict__ in,const float* __restrict__ image,
                        const float* __restrict__ pred,
                        int IH,int IW,int OH,int OW,
                        const float* __restrict__ wt,const float* __restrict__ bias,
                        int inHW,const float* __restrict__ gamIn,const float* __restrict__ betIn,
                        float* __restrict__ outp,
                        float* s_wt,float* s_misc,int T,int tid){
    if(INMODE==2) prep_gn(GNIN,inHW,gamIn,betIn,s_misc,0);
    if(INMODE==1){
        if(threadIdx.x<BB){
            float m=__uint_as_float(d_simgU[threadIdx.x]);
            s_misc[80+threadIdx.x]=fminf(fmaxf(m,1e-5f),1.0f);
        }
    }
    for(int i=threadIdx.x;i<OC*IC*K*K;i+=blockDim.x){
        int oc=i/(IC*K*K); int rest=i-oc*IC*K*K;
        s_wt[rest*OC+oc]=wt[i];
    }
    __syncthreads();

    double g0s=0,g0q=0,g1s=0,g1q=0,g2s=0,g2q=0,g3s=0,g3q=0;
    const int OWg=OW>>1;
    for(int idx=tid; idx<BB*OH*OWg; idx+=T){
        int xg=idx%OWg; int r2=idx/OWg; int oy=r2%OH; int b=r2/OH;
        int ox=xg<<1;
        float a0[OC],a1[OC];
#pragma unroll
        for(int oc=0;oc<OC;oc++){float bv=bias[oc]; a0[oc]=bv; a1[oc]=bv;}
        for(int ic=0;ic<IC;ic++){
#pragma unroll
            for(int ky=0;ky<K;ky++){
                int iy=oy*S-1+ky;
                if(EDGE) iy=min(max(iy,0),IH-1);
                else if(iy<0||iy>=IH) continue;
#pragma unroll
                for(int kx=0;kx<K;kx++){
                    int ix0=ox*S-1+kx, ix1=ix0+S;
                    float v0,v1;
                    if(EDGE){
                        int j0=min(max(ix0,0),IW-1), j1=min(max(ix1,0),IW-1);
                        v0=rd<INMODE,IC>(in,image,pred,s_misc,b,ic,iy,j0,IH,IW);
                        v1=rd<INMODE,IC>(in,image,pred,s_misc,b,ic,iy,j1,IH,IW);
                    }else{
                        v0=(ix0>=0&&ix0<IW)? rd<INMODE,IC>(in,image,pred,s_misc,b,ic,iy,ix0,IH,IW):0.f;
                        v1=(ix1>=0&&ix1<IW)? rd<INMODE,IC>(in,image,pred,s_misc,b,ic,iy,ix1,IH,IW):0.f;
                    }
                    const float* w=&s_wt[((ic*K+ky)*K+kx)*OC];
#pragma unroll
                    for(int oc=0;oc<OC;oc++){
                        a0[oc]=fmaf(v0,w[oc],a0[oc]);
                        a1[oc]=fmaf(v1,w[oc],a1[oc]);
                    }
                }
            }
        }
        double slo=0,sql=0,shi=0,sqh=0;
#pragma unroll
        for(int oc=0;oc<OC;oc++){
            float* o=&outp[((size_t)(b*OC+oc)*OH+oy)*OW+ox];
            o[0]=a0[oc]; o[1]=a1[oc];
            if(GNOUT>=0){
                double dd0=a0[oc], dd1=a1[oc];
                if(oc<8){slo+=dd0+dd1; sql+=dd0*dd0+dd1*dd1;}
                else    {shi+=dd0+dd1; sqh+=dd0*dd0+dd1*dd1;}
            }
        }
        if(GNOUT>=0){
            if(b==0){g0s+=slo;g0q+=sql;g1s+=shi;g1q+=sqh;}
            else    {g2s+=slo;g2q+=sql;g3s+=shi;g3q+=sqh;}
        }
    }
    if(GNOUT>=0){
        double acc[8]={g0s,g0q,g1s,g1q,g2s,g2q,g3s,g3q};
        slotAdd8(acc,d_gnS[GNOUT]);
    }
}

// coords for one pixel (feature-based 5D bilateral coords)
__device__ __forceinline__ void pix_coords(const float* __restrict__ feature,int b,int pix,
                                           float s,int* c){
    float r  = (feature[(size_t)(b*3+0)*NN+pix]/s)*255.0f;
    float g  = (feature[(size_t)(b*3+1)*NN+pix]/s)*255.0f;
    float bl = (feature[(size_t)(b*3+2)*NN+pix]/s)*255.0f;
    int i = pix/WW, j = pix - i*WW;
    float Y = fmaf(bl,0.114f,    fmaf(g,0.587f,    r*0.299f));
    float U = fmaf(bl,0.5f,      fmaf(g,-0.331264f,r*(-0.168736f)))+128.0f;
    float V = fmaf(bl,-0.081312f,fmaf(g,-0.418688f,r*0.5f))+128.0f;
    c[0]=(int)floorf((float)j/7.0f);
    c[1]=(int)floorf((float)i/7.0f);
    c[2]=(int)floorf(Y*0.125f);
    c[3]=(int)floorf(U*0.5f);
    c[4]=(int)floorf(V*0.5f);
}

__device__ __forceinline__ int hash5i(const int* c){
    unsigned s = (unsigned)c[0]*73856093u + (unsigned)c[1]*19349663u + (unsigned)c[2]*83492791u
               + (unsigned)c[3]*49979687u + (unsigned)c[4]*24036583u;
    return (int)(s & (unsigned)TMASK);
}

__device__ __forceinline__ unsigned long long pack5(const int* c){
    unsigned long long k=0;
#pragma unroll
    for(int d=0;d<5;d++) k |= ((unsigned long long)(unsigned)(c[d]+1)) << (12*d);
    return k;
}

// ------------------------- THE kernel -------------------------
__global__ void __launch_bounds__(512) k_all(
    const float* __restrict__ image,const float* __restrict__ feature,const float* __restrict__ pred,
    const float* __restrict__ w1,const float* __restrict__ b1,const float* __restrict__ g1,const float* __restrict__ be1,
    const float* __restrict__ w2,const float* __restrict__ b2,const float* __restrict__ g2,const float* __restrict__ be2,
    const float* __restrict__ wd1,const float* __restrict__ bd1,const float* __restrict__ gd1,const float* __restrict__ bed1,
    const float* __restrict__ wd2,const float* __restrict__ bd2,const float* __restrict__ gd2,const float* __restrict__ bed2,
    const float* __restrict__ wf,const float* __restrict__ bf,
    float* __restrict__ out)
{
    const int T   = blockDim.x*gridDim.x;
    const int tid = blockIdx.x*blockDim.x + threadIdx.x;

    __shared__ float s_wt[4608];
    __shared__ float s_misc[128];
    __shared__ float s_alpha[6], s_beta[6];

    const unsigned PRIME[5]={73856093u,19349663u,83492791u,49979687u,24036583u};

    // ================= P0: clears =================
    for(int i=tid;i<BB*TT;i+=T) d_winner[i]=-1;
    for(int i=tid;i<BB*TT;i+=T) d_ctabP[i]=0xFFFFFFFFFFFFFFFFULL;
    if(tid<BB) d_Mcnt[tid]=0;
    if(tid>=8 && tid<8+32)   ((double*)d_gnS)[tid-8]=0.0;
    if(tid>=64 && tid<64+104)((double*)d_rzS)[tid-64]=0.0;
    if(tid>=192 && tid<192+96)((double*)d_papS)[tid-192]=0.0;
    if(tid==300) d_cmaxU=0u;
    if(tid>=301&&tid<301+BB) d_simgU[tid-301]=0u;
    if(tid>=303&&tid<303+BB) d_sfeatU[tid-303]=0u;
    for(int i=tid;i<BB*NN;i+=T){
        d_cnt[i]=0.f; d_ws[i]=0.f;
        d_b4[i]=make_float4(0.f,0.f,0.f,0.f);
    }
    gridbar();

    // ================= P1: image/feature maxes =================
    {
        float mi0=0.f,mi1=0.f,mf0=0.f,mf1=0.f;
        for(int i=tid;i<BB*3*NN;i+=T){
            float v=image[i], w=feature[i];
            if(i<3*NN){ mi0=fmaxf(mi0,v); mf0=fmaxf(mf0,w); }
            else      { mi1=fmaxf(mi1,v); mf1=fmaxf(mf1,w); }
        }
        blockMaxAtomic(mi0,&d_simgU[0]);
        blockMaxAtomic(mi1,&d_simgU[1]);
        blockMaxAtomic(mf0,&d_sfeatU[0]);
        blockMaxAtomic(mf1,&d_sfeatU[1]);
    }
    gridbar();

    // ================= P2: conv1 + hash =================
    conv_ph<6,16,4,2,true,1,0,0>(nullptr,image,pred,HH,WW,H1,W1,w1,b1,
                                 0,nullptr,nullptr,d_x1,s_wt,s_misc,T,tid);
    for(int w=tid;w<BB*NN;w+=T){
        int b=(w>=NN); int pix=w-(b?NN:0);
        float sf=fminf(fmaxf(__uint_as_float(d_sfeatU[b]),1e-5f),1.0f);
        int c[5]; pix_coords(feature,b,pix,sf,c);
        int h=hash5i(c);
        d_pixh[w]=h;
        d_pixkey[w]=(long long)pack5(c);
        atomicMax(&d_winner[b*TT+h],pix);
    }
    gridbar();

    // ================= P3: conv2 + ctab =================
    conv_ph<16,16,4,2,true,2,0,1>(d_x1,nullptr,nullptr,H1,W1,H2,W2,w2,b2,
                                  H1*W1,g1,be1,d_x2,s_wt,s_misc,T,tid);
    for(int w=tid;w<BB*NN;w+=T){
        int b=(w>=NN); int pix=w-(b?NN:0);
        int h=d_pixh[w];
        if(d_winner[b*TT+h]==pix)
            d_ctabP[b*TT+h]=(unsigned long long)d_pixkey[w];
    }
    gridbar();

    // ================= P4: convd1 + compact =================
    conv_ph<16,16,3,1,false,2,1,2>(d_x2,nullptr,nullptr,H2,W2,H2,W2,wd1,bd1,
                                   H2*W2,g2,be2,d_dx1,s_wt,s_misc,T,tid);
    {
        int ln=threadIdx.x&31;
        for(int i0=0;i0<BB*TT;i0+=T){
            int i=i0+tid;
            bool on = (i<BB*TT) && (d_winner[i]>=0);
            unsigned m=__ballot_sync(0xffffffffu,on);
            if(m){
                int leader=__ffs(m)-1;
                int wbase = i0 + blockIdx.x*blockDim.x + (threadIdx.x & ~31);
                int bb_ = (wbase + leader)>>20;
                int base=0;
                if(ln==leader) base=atomicAdd(&d_Mcnt[bb_],__popc(m));
                base=__shfl_sync(0xffffffffu,base,leader);
                if(on){
                    int a=base+__popc(m & ((1u<<ln)-1u));
                    d_actcell[bb_*NN+a]=i&TMASK;
                    d_cell2act[i]=a;
                }
            }
        }
    }
    gridbar();

    // ================= P5: catb (resize dx1 + copy x1) + nbr build =================
    prep_gn(2,H2*W2,gd1,bed1,s_misc,0);    // layer gnd1 for dx1
    prep_gn(0,H1*W1,g1,be1,s_misc,40);     // layer gn1 for x1
    __syncthreads();
    for(int i=tid;i<BB*16*H1*W1;i+=T){     // upper 16 ch: resize2x(gn(dx1))
        int ox=i%W1; int r2=i/W1; int oy=r2%H1; r2/=H1;
        int c=r2%16; int b=r2/16;
        float cy=oy*0.5f-0.25f, cx=ox*0.5f-0.25f;
        int y0=(int)floorf(cy); float fy=cy-(float)y0;
        int x0=(int)floorf(cx); float fx=cx-(float)x0;
        int y1=min(y0+1,H2-1), x1=min(x0+1,W2-1);
        y0=max(y0,0); x0=max(x0,0);
        const float* ip=d_dx1+((size_t)(b*16+c))*H2*W2;
        float v00=gn_apply(ip[y0*W2+x0],b,c,s_misc,0);
        float v01=gn_apply(ip[y0*W2+x1],b,c,s_misc,0);
        float v10=gn_apply(ip[y1*W2+x0],b,c,s_misc,0);
        float v11=gn_apply(ip[y1*W2+x1],b,c,s_misc,0);
        float top=v00+fx*(v01-v00), bot=v10+fx*(v11-v10);
        d_catb[((size_t)(b*32+c)*H1+oy)*W1+ox]=top+fy*(bot-top);
    }
    for(int i=tid;i<BB*16*H1*W1;i+=T){     // lower 16 ch: gn(x1)
        int p=i%(H1*W1); int c=(i/(H1*W1))&15; int b=i/(16*H1*W1);
        float v=gn_apply(d_x1[((size_t)(b*16+c))*H1*W1+p],b,c,s_misc,40);
        d_catb[((size_t)(b*32+16+c))*H1*W1+p]=v;
    }
    for(int w=tid;w<BB*NN;w+=T){           // neighbor table
        int b=(w>=NN); int a=w-(b?NN:0);
        if(a<d_Mcnt[b]){
            int cell=d_actcell[b*NN+a];
            unsigned long long key=d_ctabP[b*TT+cell];
            int* nb=&d_nbr[(size_t)(b*NN+a)*10];
            int k=0;
#pragma unroll
            for(int d=0;d<5;d++){
#pragma unroll
                for(int o=0;o<2;o++){
                    unsigned nh = ((unsigned)cell + (o? PRIME[d] : (0u-PRIME[d]))) & (unsigned)TMASK;
                    unsigned long long keyN = o? key+(1ULL<<(12*d)) : key-(1ULL<<(12*d));
                    int res=-1;
                    if(d_ctabP[b*TT+(int)nh]==keyN) res=d_cell2act[b*TT+(int)nh];
                    nb[k++]=res;
                }
            }
            d_nA[b*NN+a]=1.0f;
        }
    }
    gridbar();

    // ================= P6: convd2 =================
    conv_ph<32,16,3,1,false,0,0,3>(d_catb,nullptr,nullptr,H1,W1,H1,W1,wd2,bd2,
                                   0,nullptr,nullptr,d_dx2,s_wt,s_misc,T,tid);
    gridbar();

    // ================= P7: resize2 (gn(dx2) -> dx2up) =================
    prep_gn(3,H1*W1,gd2,bed2,s_misc,0);
    __syncthreads();
    for(int i=tid;i<BB*16*NN;i+=T){
        int ox=i%WW; int r2=i/WW; int oy=r2%HH; r2/=HH;
        int c=r2%16; int b=r2/16;
        float cy=oy*0.5f-0.25f, cx=ox*0.5f-0.25f;
        int y0=(int)floorf(cy); float fy=cy-(float)y0;
        int x0=(int)floorf(cx); float fx=cx-(float)x0;
        int y1=min(y0+1,H1-1), x1=min(x0+1,W1-1);
        y0=max(y0,0); x0=max(x0,0);
        const float* ip=d_dx2+((size_t)(b*16+c))*H1*W1;
        float v00=gn_apply(ip[y0*W1+x0],b,c,s_misc,0);
        float v01=gn_apply(ip[y0*W1+x1],b,c,s_misc,0);
        float v10=gn_apply(ip[y1*W1+x0],b,c,s_misc,0);
        float v11=gn_apply(ip[y1*W1+x1],b,c,s_misc,0);
        float top=v00+fx*(v01-v00), bot=v10+fx*(v11-v10);
        d_dx2up[((size_t)(b*16+c)*HH+oy)*WW+ox]=top+fy*(bot-top);
    }
    gridbar();

    // ================= P8: convf (conf = 0.5*(tanh+1)) + conf max =================
    for(int i=threadIdx.x;i<144;i+=blockDim.x) s_wt[i]=wf[i];
    __syncthreads();
    {
        float bias0=bf[0];
        float lmax=0.f;
        for(int idx=tid; idx<BB*NN; idx+=T){
            int ox=idx%WW; int r2=idx/WW; int oy=r2%HH; int b=r2/HH;
            float acc=bias0;
            for(int ic=0;ic<16;ic++){
                const float* ip=d_dx2up+((size_t)(b*16+ic))*NN;
#pragma unroll
                for(int ky=0;ky<3;ky++){
                    int iy=min(max(oy-1+ky,0),HH-1);
#pragma unroll
                    for(int kx=0;kx<3;kx++){
                        int ix=min(max(ox-1+kx,0),WW-1);
                        acc=fmaf(ip[iy*WW+ix], s_wt[(ic*3+ky)*3+kx], acc);
                    }
                }
            }
            float cf=0.5f*(tanhf(acc)+1.0f);
            d_conf[idx]=cf;
            lmax=fmaxf(lmax,cf);
        }
        blockMaxAtomic(lmax,&d_cmaxU);
    }
    gridbar();

    // ================= P9: splat =================
    {
        float cmax=fmaxf(__uint_as_float(d_cmaxU),1e-5f);
        for(int w=tid;w<BB*NN;w+=T){
            int b=(w>=NN); int pix=w-(b?NN:0);
            int h=d_pixh[w];
            int a=d_cell2act[b*TT+h];
            d_pixa[w]=a;
            int base=b*NN+a;
            float wgt=d_conf[w]/cmax;
            atomicAdd(&d_cnt[base],1.0f);
            atomicAdd(&d_ws[base],wgt);
            float p0=pred[(size_t)(b*3+0)*NN+pix];
            float p1=pred[(size_t)(b*3+1)*NN+pix];
            float p2=pred[(size_t)(b*3+2)*NN+pix];
            atomicAdd(&d_b4[base].x, wgt*p0);
            atomicAdd(&d_b4[base].y, wgt*p1);
            atomicAdd(&d_b4[base].z, wgt*p2);
        }
    }
    gridbar();

    // ================= P10..19: bistochastization x10 =================
    for(int it=0;it<10;it++){
        const float* src = (it&1)? d_nB : d_nA;
        float*       dst = (it&1)? d_nA : d_nB;
        for(int w=tid;w<BB*NN;w+=T){
            int b=(w>=NN); int a=w-(b?NN:0);
            if(a<d_Mcnt[b]){
                int base=b*NN+a;
                const int* nb=&d_nbr[(size_t)base*10];
                float v=src[base];
                float s=10.0f*v;
#pragma unroll
                for(int k=0;k<10;k++){
                    int id=nb[k];
                    if(id>=0) s+=src[b*NN+id];
                }
                dst[base]=sqrtf(v*d_cnt[base]/(s+1e-12f));
            }
        }
        gridbar();
    }

    // ================= P20: prep (diag, minv, edge weights, x0) =================
    for(int w=tid;w<BB*NN;w+=T){
        int b=(w>=NN); int a=w-(b?NN:0);
        if(a<d_Mcnt[b]){
            int base=b*NN+a;
            const int* nb=&d_nbr[(size_t)base*10];
            float* ew=&d_ew[(size_t)base*10];
            float n=d_nA[base];
            float s=10.0f*n;
#pragma unroll
            for(int k=0;k<10;k++){
                int id=nb[k];
                if(id>=0){
                    float nk=d_nA[b*NN+id];
                    s+=nk;
                    ew[k]=200.0f*n*nk;
                }
            }
            float mm=n*s;
            float ws=d_ws[base];
            float dg=200.0f*(mm-10.0f*n*n)+ws;
            d_diag[base]=dg;
            d_minv[base]=1.0f/fmaxf(dg,1e-5f);
            float4 bb=d_b4[base];
            float inv=ws+1e-12f;
            d_x4[base]=make_float4(bb.x/inv,bb.y/inv,bb.z/inv,0.f);
        }
    }
    gridbar();

    // ================= P21: CG init =================
    {
        double acc[8]={0,0,0,0,0,0,0,0};
        for(int w=tid;w<BB*NN;w+=T){
            int b=(w>=NN); int a=w-(b?NN:0);
            if(a<d_Mcnt[b]){
                int base=b*NN+a;
                const int* nb=&d_nbr[(size_t)base*10];
                const float* ew=&d_ew[(size_t)base*10];
                float4 x=d_x4[base];
                float t0=0.f,t1=0.f,t2=0.f;
#pragma unroll
                for(int k=0;k<10;k++){
                    int id=nb[k];
                    if(id>=0){
                        float e=ew[k];
                        float4 q=d_x4[b*NN+id];
                        t0=fmaf(e,q.x,t0); t1=fmaf(e,q.y,t1); t2=fmaf(e,q.z,t2);
                    }
                }
                float dg=d_diag[base];
                float A0=dg*x.x-t0, A1=dg*x.y-t1, A2=dg*x.z-t2;
                float4 bb=d_b4[base];
                float r0=bb.x-A0, r1=bb.y-A1, r2=bb.z-A2;
                float mi=d_minv[base];
                float z0=mi*r0, z1=mi*r1, z2=mi*r2;
                d_r4[base]=make_float4(r0,r1,r2,0.f);
                d_z4[base]=make_float4(z0,z1,z2,0.f);
                d_p4[base]=make_float4(z0,z1,z2,0.f);
                int c=b*3;
                acc[c+0]+=(double)r0*z0; acc[c+1]+=(double)r1*z1; acc[c+2]+=(double)r2*z2;
            }
        }
        slotAdd8(acc, d_rzS[0]);
    }
    gridbar();

    // ================= CG iterations =================
    for(int it=0;it<12;it++){
        // A-phase
        {
            double acc[8]={0,0,0,0,0,0,0,0};
            for(int w=tid;w<BB*NN;w+=T){
                int b=(w>=NN); int a=w-(b?NN:0);
                if(a<d_Mcnt[b]){
                    int base=b*NN+a;
                    const int* nb=&d_nbr[(size_t)base*10];
                    const float* ew=&d_ew[(size_t)base*10];
                    float4 p=d_p4[base];
                    float t0=0.f,t1=0.f,t2=0.f;
#pragma unroll
                    for(int k=0;k<10;k++){
                        int id=nb[k];
                        if(id>=0){
                            float e=ew[k];
                            float4 q=d_p4[b*NN+id];
                            t0=fmaf(e,q.x,t0); t1=fmaf(e,q.y,t1); t2=fmaf(e,q.z,t2);
                        }
                    }
                    float dg=d_diag[base];
                    float A0=dg*p.x-t0, A1=dg*p.y-t1, A2=dg*p.z-t2;
                    d_Ap4[base]=make_float4(A0,A1,A2,0.f);
                    int c=b*3;
                    acc[c+0]+=(double)p.x*A0; acc[c+1]+=(double)p.y*A1; acc[c+2]+=(double)p.z*A2;
                }
            }
            slotAdd8(acc, d_papS[it]);
        }
        gridbar();

        // U1
        {
            if(threadIdx.x<6)
                s_alpha[threadIdx.x]=(float)d_rzS[it][threadIdx.x]/((float)d_papS[it][threadIdx.x]+1e-12f);
            __syncthreads();
            double acc[8]={0,0,0,0,0,0,0,0};
            for(int w=tid;w<BB*NN;w+=T){
                int b=(w>=NN); int a=w-(b?NN:0);
                if(a<d_Mcnt[b]){
                    int base=b*NN+a;
                    int c=b*3;
                    float al0=s_alpha[c+0], al1=s_alpha[c+1], al2=s_alpha[c+2];
                    float4 p=d_p4[base], Ap=d_Ap4[base], x=d_x4[base], r=d_r4[base];
                    x.x+=al0*p.x; x.y+=al1*p.y; x.z+=al2*p.z;
                    r.x-=al0*Ap.x; r.y-=al1*Ap.y; r.z-=al2*Ap.z;
                    float mi=d_minv[base];
                    float z0=mi*r.x, z1=mi*r.y, z2=mi*r.z;
                    d_x4[base]=x; d_r4[base]=r;
                    d_z4[base]=make_float4(z0,z1,z2,0.f);
                    acc[c+0]+=(double)r.x*z0; acc[c+1]+=(double)r.y*z1; acc[c+2]+=(double)r.z*z2;
                }
            }
            slotAdd8(acc, d_rzS[it+1]);
        }
        gridbar();

        // U2
        {
            if(threadIdx.x<6)
                s_beta[threadIdx.x]=(float)d_rzS[it+1][threadIdx.x]/((float)d_rzS[it][threadIdx.x]+1e-12f);
            __syncthreads();
            for(int w=tid;w<BB*NN;w+=T){
                int b=(w>=NN); int a=w-(b?NN:0);
                if(a<d_Mcnt[b]){
                    int base=b*NN+a;
                    int c=b*3;
                    float4 z=d_z4[base], p=d_p4[base];
                    p.x=z.x+s_beta[c+0]*p.x;
                    p.y=z.y+s_beta[c+1]*p.y;
                    p.z=z.z+s_beta[c+2]*p.z;
                    d_p4[base]=p;
                }
            }
        }
        gridbar();
    }

    // ================= output =================
    {
        float cmax=fmaxf(__uint_as_float(d_cmaxU),1e-5f);
        for(int w=tid;w<BB*NN;w+=T){
            int b=(w>=NN); int pix=w-(b?NN:0);
            int a=d_pixa[w];
            float4 x=d_x4[b*NN+a];
            out[(size_t)(b*3+0)*NN+pix]=x.x;
            out[(size_t)(b*3+1)*NN+pix]=x.y;
            out[(size_t)(b*3+2)*NN+pix]=x.z;
            out[(size_t)BB*3*NN + w]=d_conf[w]/cmax;
        }
    }
}

// ------------------------- host -------------------------
extern "C" void kernel_launch(void* const* d_in, const int* in_sizes, int n_in,
                              void* d_out, int out_size){
    const float* image  =(const float*)d_in[0];
    const float* feature=(const float*)d_in[1];
    const float* pred   =(const float*)d_in[2];
    const float* w1 =(const float*)d_in[3];  const float* b1 =(const float*)d_in[4];
    const float* g1 =(const float*)d_in[5];  const float* be1=(const float*)d_in[6];
    const float* w2 =(const float*)d_in[7];  const float* b2 =(const float*)d_in[8];
    const float* g2 =(const float*)d_in[9];  const float* be2=(const float*)d_in[10];
    const float* wd1=(const float*)d_in[11]; const float* bd1=(const float*)d_in[12];
    const float* gd1=(const float*)d_in[13]; const float* bed1=(const float*)d_in[14];
    const float* wd2=(const float*)d_in[15]; const float* bd2=(const float*)d_in[16];
    const float* gd2=(const float*)d_in[17]; const float* bed2=(const float*)d_in[18];
    const float* wf =(const float*)d_in[19]; const float* bf =(const float*)d_in[20];
    float* out=(float*)d_out;

    int sm=0; cudaDeviceGetAttribute(&sm, cudaDevAttrMultiProcessorCount, 0);
    int occ=0; cudaOccupancyMaxActiveBlocksPerMultiprocessor(&occ, k_all, 512, 0);
    if(occ<1) occ=1;
    int G = sm*occ;
    if(G>MAXG) G=MAXG;
    G &= ~7;
    if(G<8) G=8;

    k_all<<<G,512>>>(image,feature,pred,
                     w1,b1,g1,be1, w2,b2,g2,be2,
                     wd1,bd1,gd1,bed1, wd2,bd2,gd2,bed2,
                     wf,bf, out);
}